// round 12
// baseline (speedup 1.0000x reference)
#include <cuda_runtime.h>
#include <cuda_fp16.h>
#include <cuda_bf16.h>

#define NN 50000
#define EE 800000
#define DD 128
#define OO 64
#define LL 3

// ---------------- scratch (device globals) ----------------
__device__ __half g_hx[NN * DD];      // x converted to fp16
__device__ __half g_h0[NN * DD];
__device__ __half g_h1[NN * DD];
__device__ __half g_agg0[NN * DD];    // (1-a)/deg * sum_{src->dst}
__device__ __half g_agg1[NN * DD];    // a/deg * sum_{dst->src}
__device__ __half g_hmax[NN * DD];
__device__ __half g_Wt[LL * 3 * DD * DD];   // layer weights fp16, [mat][n][k]
__device__ __half g_Wlt[OO * DD];           // Wlin fp16, [n][k]

__device__ int g_deg[2 * NN];         // [0]=by dst, [1]=by src
__device__ int g_rp0[NN + 1];
__device__ int g_rp1[NN + 1];
__device__ int g_cur0[NN];
__device__ int g_cur1[NN];
__device__ int g_col0[EE];            // CSR by dst, values = src
__device__ int g_col1[EE];            // CSR by src, values = dst

// ---------------- cp.async helper ----------------
__device__ __forceinline__ void cp16(__half* s, const void* g, bool v) {
    unsigned sa = (unsigned)__cvta_generic_to_shared(s);
    int sz = v ? 16 : 0;
    asm volatile("cp.async.ca.shared.global [%0], [%1], 16, %2;"
                 :: "r"(sa), "l"(g), "r"(sz));
}

// ---------------- CSR build ----------------
__global__ void count_kernel(const int* __restrict__ ei, int E) {
    int e = blockIdx.x * blockDim.x + threadIdx.x;
    if (e >= E) return;
    int src = ei[e];
    int dst = ei[E + e];
    atomicAdd(&g_deg[dst], 1);
    atomicAdd(&g_deg[NN + src], 1);
}

__global__ void scan_kernel(int n) {
    const int* deg = g_deg + blockIdx.x * NN;
    int* rp = (blockIdx.x == 0) ? g_rp0 : g_rp1;
    int* cur = (blockIdx.x == 0) ? g_cur0 : g_cur1;

    __shared__ int sums[1024];
    int t = threadIdx.x;
    int chunk = (n + 1023) / 1024;
    int begin = t * chunk;
    int end = min(begin + chunk, n);
    int s = 0;
    for (int i = begin; i < end; i++) s += deg[i];
    sums[t] = s;
    __syncthreads();
    for (int off = 1; off < 1024; off <<= 1) {
        int v = (t >= off) ? sums[t - off] : 0;
        __syncthreads();
        sums[t] += v;
        __syncthreads();
    }
    int prefix = (t == 0) ? 0 : sums[t - 1];
    for (int i = begin; i < end; i++) {
        rp[i] = prefix;
        cur[i] = prefix;
        prefix += deg[i];
    }
    if (t == 1023) rp[n] = prefix;
}

// fused: CSR fill | x->fp16 convert | weight transpose+convert
__global__ void fill_convert_prep_kernel(
    const int* __restrict__ ei, int E,
    const float* __restrict__ x, int total4,
    const float* __restrict__ Wself, const float* __restrict__ Wstd,
    const float* __restrict__ Wdts, const float* __restrict__ Wlin,
    int fillBlocks, int convBlocks)
{
    int b = blockIdx.x;
    if (b < fillBlocks) {
        int e = b * blockDim.x + threadIdx.x;
        if (e >= E) return;
        int src = ei[e];
        int dst = ei[E + e];
        int p0 = atomicAdd(&g_cur0[dst], 1);
        g_col0[p0] = src;
        int p1 = atomicAdd(&g_cur1[src], 1);
        g_col1[p1] = dst;
    } else if (b < fillBlocks + convBlocks) {
        int i = (b - fillBlocks) * blockDim.x + threadIdx.x;
        if (i >= total4) return;
        float4 v = ((const float4*)x)[i];
        __half2 h0 = __floats2half2_rn(v.x, v.y);
        __half2 h1 = __floats2half2_rn(v.z, v.w);
        uint2 u;
        u.x = *(unsigned*)&h0;
        u.y = *(unsigned*)&h1;
        ((uint2*)g_hx)[i] = u;
    } else {
        int idx = (b - fillBlocks - convBlocks) * blockDim.x + threadIdx.x;
        if (idx < LL * 3 * DD * DD) {
            int mat = idx >> 14;
            int r = (idx >> 7) & 127;
            int c = idx & 127;
            int l = mat / 3, s = mat % 3;
            const float* W = (s == 0) ? Wself : (s == 1) ? Wstd : Wdts;
            float v = W[(size_t)l * DD * DD + r * DD + c];
            g_Wt[(size_t)mat * DD * DD + c * DD + r] = __float2half(v);
        } else {
            int i2 = idx - LL * 3 * DD * DD;
            if (i2 < OO * DD) {
                int n = i2 >> 7;
                int k = i2 & 127;
                g_Wlt[n * DD + k] = __float2half(Wlin[k * OO + n]);
            }
        }
    }
}

// ---------------- aggregation: one warp per node, 4-deep fp16 tree ---------
__device__ __forceinline__ __half2 u2h(unsigned u) { return *(__half2*)&u; }

__global__ void agg_kernel(const __half* __restrict__ h,
                           const float* __restrict__ alpha, int M) {
    int gw = (blockIdx.x * blockDim.x + threadIdx.x) >> 5;
    if (gw >= M) return;
    int lane = threadIdx.x & 31;
    int base = lane * 4;   // halves
    float a = alpha[0];

    #pragma unroll
    for (int dir = 0; dir < 2; dir++) {
        const int* rp  = dir ? g_rp1  : g_rp0;
        const int* col = dir ? g_col1 : g_col0;
        __half* out    = dir ? g_agg1 : g_agg0;
        float coef     = dir ? a : (1.f - a);

        int s = rp[gw], e = rp[gw + 1];
        float4 acc = make_float4(0.f, 0.f, 0.f, 0.f);
        int i = s;
        for (; i + 3 < e; i += 4) {
            int n0 = col[i],     n1 = col[i + 1];
            int n2 = col[i + 2], n3 = col[i + 3];
            uint2 u0 = *(const uint2*)(h + (size_t)n0 * DD + base);
            uint2 u1 = *(const uint2*)(h + (size_t)n1 * DD + base);
            uint2 u2 = *(const uint2*)(h + (size_t)n2 * DD + base);
            uint2 u3 = *(const uint2*)(h + (size_t)n3 * DD + base);
            __half2 s0 = __hadd2(__hadd2(u2h(u0.x), u2h(u1.x)),
                                 __hadd2(u2h(u2.x), u2h(u3.x)));
            __half2 s1 = __hadd2(__hadd2(u2h(u0.y), u2h(u1.y)),
                                 __hadd2(u2h(u2.y), u2h(u3.y)));
            float2 f0 = __half22float2(s0);
            float2 f1 = __half22float2(s1);
            acc.x += f0.x; acc.y += f0.y;
            acc.z += f1.x; acc.w += f1.y;
        }
        for (; i < e; i++) {
            int n0 = col[i];
            uint2 u0 = *(const uint2*)(h + (size_t)n0 * DD + base);
            float2 f0 = __half22float2(u2h(u0.x));
            float2 f1 = __half22float2(u2h(u0.y));
            acc.x += f0.x; acc.y += f0.y;
            acc.z += f1.x; acc.w += f1.y;
        }
        float sc = coef / fmaxf((float)(e - s), 1.f);
        __half2 o0 = __floats2half2_rn(acc.x * sc, acc.y * sc);
        __half2 o1 = __floats2half2_rn(acc.z * sc, acc.w * sc);
        uint2 u;
        u.x = *(unsigned*)&o0;
        u.y = *(unsigned*)&o1;
        *(uint2*)(out + (size_t)gw * DD + base) = u;
    }
}

// ---------------- fp16 tensor-core layer GEMM (cp.async, BK=64) ------------
// [h|agg0|agg1](Mx384 fp16) @ Wt(384x128 fp16, [n][k]). 8 warps (4x2),
// warp tile 32x64, mma.m16n8k16, 6 chunks of K=64, ONE barrier per chunk.
#define SA 72   // smem row stride in halves (64 + 8 pad; conflict-free)

__global__ __launch_bounds__(256) void gemm_layer_f16(
    const __half* __restrict__ A0,
    const __half* __restrict__ Wt,   // layer base (3 mats)
    const float* __restrict__ bs0,
    const float* __restrict__ bs1,
    const float* __restrict__ bs2,
    const float* __restrict__ alpha,
    __half* __restrict__ Hout,
    int firstLayer, int M)
{
    __shared__ __align__(16) __half As[2][128 * SA];
    __shared__ __align__(16) __half Bs[2][128 * SA];
    __shared__ float bias_s[DD];

    int tid = threadIdx.x;
    int block_row = blockIdx.x * 128;
    int warpId = tid >> 5;
    int lane = tid & 31;
    int g = lane >> 2;
    int t = lane & 3;
    int warp_row = warpId & 3;
    int warp_col = warpId >> 2;

    if (tid < DD) {
        float a = alpha[0];
        bias_s[tid] = bs0[tid] + (1.f - a) * bs1[tid] + a * bs2[tid];
    }

    float acc[2][8][4];
    #pragma unroll
    for (int mt = 0; mt < 2; mt++)
        #pragma unroll
        for (int nt = 0; nt < 8; nt++)
            #pragma unroll
            for (int r = 0; r < 4; r++) acc[mt][nt][r] = 0.f;

    const __half* Aseg[3] = { A0, g_agg0, g_agg1 };

    // chunk = 128 rows x 64 halves; 1024 16B-chunks per matrix, 4 per thread
    int l_row = tid >> 1;            // 0..127
    int l_c16 = (tid & 1) * 4;       // 16B-chunk index base (0 or 4)

    auto cp_chunk = [&](int c, int buf) {
        int seg = c >> 1;
        int kl = (c & 1) * 64;       // halves
        const __half* A = Aseg[seg];
        const __half* B = Wt + (size_t)seg * DD * DD;
        int gr = block_row + l_row;
        #pragma unroll
        for (int j = 0; j < 4; j++) {
            int q = (l_c16 + j) * 8; // half offset within 64
            cp16(&As[buf][l_row * SA + q], A + (size_t)gr * DD + kl + q, gr < M);
            cp16(&Bs[buf][l_row * SA + q], B + (size_t)l_row * DD + kl + q, true);
        }
        asm volatile("cp.async.commit_group;");
    };

    cp_chunk(0, 0);

    #pragma unroll 1
    for (int c = 0; c < 6; c++) {
        int buf = c & 1;
        asm volatile("cp.async.wait_group 0;");
        __syncthreads();
        if (c < 5) cp_chunk(c + 1, buf ^ 1);   // overlaps with MMA below

        #pragma unroll
        for (int ks = 0; ks < 4; ks++) {
            int k0 = ks * 16;
            unsigned af[2][4];
            #pragma unroll
            for (int mt = 0; mt < 2; mt++) {
                int mrow = warp_row * 32 + mt * 16;
                const __half* base = &As[buf][0];
                af[mt][0] = *(const unsigned*)&base[(mrow + g) * SA + k0 + 2 * t];
                af[mt][1] = *(const unsigned*)&base[(mrow + g + 8) * SA + k0 + 2 * t];
                af[mt][2] = *(const unsigned*)&base[(mrow + g) * SA + k0 + 8 + 2 * t];
                af[mt][3] = *(const unsigned*)&base[(mrow + g + 8) * SA + k0 + 8 + 2 * t];
            }
            unsigned bf[8][2];
            #pragma unroll
            for (int nt = 0; nt < 8; nt++) {
                int n = warp_col * 64 + nt * 8 + g;
                const __half* base = &Bs[buf][0];
                bf[nt][0] = *(const unsigned*)&base[n * SA + k0 + 2 * t];
                bf[nt][1] = *(const unsigned*)&base[n * SA + k0 + 8 + 2 * t];
            }
            #pragma unroll
            for (int mt = 0; mt < 2; mt++)
                #pragma unroll
                for (int nt = 0; nt < 8; nt++) {
                    asm volatile(
                        "mma.sync.aligned.m16n8k16.row.col.f32.f16.f16.f32 "
                        "{%0,%1,%2,%3}, {%4,%5,%6,%7}, {%8,%9}, {%0,%1,%2,%3};"
                        : "+f"(acc[mt][nt][0]), "+f"(acc[mt][nt][1]),
                          "+f"(acc[mt][nt][2]), "+f"(acc[mt][nt][3])
                        : "r"(af[mt][0]), "r"(af[mt][1]), "r"(af[mt][2]), "r"(af[mt][3]),
                          "r"(bf[nt][0]), "r"(bf[nt][1]));
                }
        }
    }

    // epilogue: bias + relu + store h(fp16) + JK max(fp16)
    #pragma unroll
    for (int mt = 0; mt < 2; mt++) {
        #pragma unroll
        for (int nt = 0; nt < 8; nt++) {
            int c0 = warp_col * 64 + nt * 8 + 2 * t;
            float b0v = bias_s[c0];
            float b1v = bias_s[c0 + 1];
            #pragma unroll
            for (int rr = 0; rr < 2; rr++) {
                int r = block_row + warp_row * 32 + mt * 16 + g + rr * 8;
                if (r < M) {
                    float v0 = fmaxf(acc[mt][nt][rr * 2 + 0] + b0v, 0.f);
                    float v1 = fmaxf(acc[mt][nt][rr * 2 + 1] + b1v, 0.f);
                    __half2 hv = __floats2half2_rn(v0, v1);
                    *(__half2*)(Hout + (size_t)r * DD + c0) = hv;
                    __half2* mp = (__half2*)(g_hmax + (size_t)r * DD + c0);
                    if (firstLayer) {
                        *mp = hv;
                    } else {
                        *mp = __hmax2(*mp, hv);
                    }
                }
            }
        }
    }
}

// ---------------- final linear via fp16 MMA: hmax @ Wlt^T + blin ------------
#define SF 136

__global__ __launch_bounds__(256) void final_mma_kernel(
    const float* __restrict__ blin, float* __restrict__ out, int M)
{
    extern __shared__ char dynsm[];
    float* bias_s = (float*)dynsm;
    __half* As = (__half*)(dynsm + 256);
    __half* Bs = As + 128 * SF;

    int tid = threadIdx.x;
    int block_row = blockIdx.x * 128;
    int warpId = tid >> 5;
    int lane = tid & 31;
    int g = lane >> 2;
    int t = lane & 3;
    int warp_row = warpId & 3;
    int warp_col = warpId >> 2;

    if (tid < OO) bias_s[tid] = blin[tid];

    #pragma unroll
    for (int k = 0; k < 8; k++) {
        int idx = tid + k * 256;
        int row = idx >> 4;
        int q = (idx & 15) * 8;
        int gr = block_row + row;
        uint4 v = make_uint4(0u, 0u, 0u, 0u);
        if (gr < M) v = *(const uint4*)(g_hmax + (size_t)gr * DD + q);
        *(uint4*)&As[row * SF + q] = v;
    }
    #pragma unroll
    for (int k = 0; k < 4; k++) {
        int idx = tid + k * 256;
        int row = idx >> 4;
        int q = (idx & 15) * 8;
        *(uint4*)&Bs[row * SF + q] = *(const uint4*)(g_Wlt + row * DD + q);
    }
    __syncthreads();

    float acc[2][4][4];
    #pragma unroll
    for (int mt = 0; mt < 2; mt++)
        #pragma unroll
        for (int nt = 0; nt < 4; nt++)
            #pragma unroll
            for (int r = 0; r < 4; r++) acc[mt][nt][r] = 0.f;

    #pragma unroll
    for (int kc = 0; kc < 8; kc++) {
        int k0 = kc * 16;
        unsigned af[2][4];
        #pragma unroll
        for (int mt = 0; mt < 2; mt++) {
            int mrow = warp_row * 32 + mt * 16;
            af[mt][0] = *(const unsigned*)&As[(mrow + g) * SF + k0 + 2 * t];
            af[mt][1] = *(const unsigned*)&As[(mrow + g + 8) * SF + k0 + 2 * t];
            af[mt][2] = *(const unsigned*)&As[(mrow + g) * SF + k0 + 8 + 2 * t];
            af[mt][3] = *(const unsigned*)&As[(mrow + g + 8) * SF + k0 + 8 + 2 * t];
        }
        unsigned bf[4][2];
        #pragma unroll
        for (int nt = 0; nt < 4; nt++) {
            int n = warp_col * 32 + nt * 8 + g;
            bf[nt][0] = *(const unsigned*)&Bs[n * SF + k0 + 2 * t];
            bf[nt][1] = *(const unsigned*)&Bs[n * SF + k0 + 8 + 2 * t];
        }
        #pragma unroll
        for (int mt = 0; mt < 2; mt++)
            #pragma unroll
            for (int nt = 0; nt < 4; nt++) {
                asm volatile(
                    "mma.sync.aligned.m16n8k16.row.col.f32.f16.f16.f32 "
                    "{%0,%1,%2,%3}, {%4,%5,%6,%7}, {%8,%9}, {%0,%1,%2,%3};"
                    : "+f"(acc[mt][nt][0]), "+f"(acc[mt][nt][1]),
                      "+f"(acc[mt][nt][2]), "+f"(acc[mt][nt][3])
                    : "r"(af[mt][0]), "r"(af[mt][1]), "r"(af[mt][2]), "r"(af[mt][3]),
                      "r"(bf[nt][0]), "r"(bf[nt][1]));
            }
    }

    #pragma unroll
    for (int mt = 0; mt < 2; mt++) {
        #pragma unroll
        for (int nt = 0; nt < 4; nt++) {
            int c0 = warp_col * 32 + nt * 8 + 2 * t;
            float b0v = bias_s[c0];
            float b1v = bias_s[c0 + 1];
            #pragma unroll
            for (int rr = 0; rr < 2; rr++) {
                int r = block_row + warp_row * 32 + mt * 16 + g + rr * 8;
                if (r < M) {
                    float2 o;
                    o.x = acc[mt][nt][rr * 2 + 0] + b0v;
                    o.y = acc[mt][nt][rr * 2 + 1] + b1v;
                    *(float2*)(out + (size_t)r * OO + c0) = o;
                }
            }
        }
    }
}

// ---------------- launch ----------------
extern "C" void kernel_launch(void* const* d_in, const int* in_sizes, int n_in,
                              void* d_out, int out_size) {
    const float* x     = (const float*)d_in[0];
    const int*   ei    = (const int*)d_in[1];
    const float* Wself = (const float*)d_in[2];
    const float* bself = (const float*)d_in[3];
    const float* Wstd  = (const float*)d_in[4];
    const float* bstd  = (const float*)d_in[5];
    const float* Wdts  = (const float*)d_in[6];
    const float* bdts  = (const float*)d_in[7];
    const float* Wlin  = (const float*)d_in[8];
    const float* blin  = (const float*)d_in[9];
    const float* alpha = (const float*)d_in[10];

    int M = in_sizes[0] / DD;        // 50000
    int E = in_sizes[1] / 2;         // 800000

    __half* hx; cudaGetSymbolAddress((void**)&hx, g_hx);
    __half* h0; cudaGetSymbolAddress((void**)&h0, g_h0);
    __half* h1; cudaGetSymbolAddress((void**)&h1, g_h1);
    __half* wt; cudaGetSymbolAddress((void**)&wt, g_Wt);
    int* degp; cudaGetSymbolAddress((void**)&degp, g_deg);

    const int FINAL_SMEM = 256 + (128 * SF + 64 * SF) * 2;   // 52480
    cudaFuncSetAttribute(final_mma_kernel,
                         cudaFuncAttributeMaxDynamicSharedMemorySize, FINAL_SMEM);

    cudaMemsetAsync(degp, 0, 2 * NN * sizeof(int));

    count_kernel<<<(E + 255) / 256, 256>>>(ei, E);            // k0
    scan_kernel<<<2, 1024>>>(M);                              // k1
    int total4 = M * DD / 4;
    int fillBlocks = (E + 255) / 256;
    int convBlocks = (total4 + 255) / 256;
    int prepBlocks = (LL * 3 * DD * DD + OO * DD + 255) / 256;
    fill_convert_prep_kernel<<<fillBlocks + convBlocks + prepBlocks, 256>>>(
        ei, E, x, total4, Wself, Wstd, Wdts, Wlin, fillBlocks, convBlocks);  // k2

    // layers
    const __half* cur = hx;
    __half* bufs[2] = { h0, h1 };
    int gemm_grid = (M + 127) / 128;
    int agg_grid = (M * 32 + 255) / 256;
    for (int l = 0; l < LL; l++) {
        agg_kernel<<<agg_grid, 256>>>(cur, alpha, M);         // k3 (layer 0)
        __half* outb = bufs[l & 1];
        gemm_layer_f16<<<gemm_grid, 256>>>(                   // k4 (layer 0)
            cur,
            wt + (size_t)l * 3 * DD * DD,
            bself + (size_t)l * DD,
            bstd  + (size_t)l * DD,
            bdts  + (size_t)l * DD,
            alpha, outb, (l == 0) ? 1 : 0, M);
        cur = outb;
    }

    // final linear (fp16 MMA)
    final_mma_kernel<<<(M + 127) / 128, 256, FINAL_SMEM>>>(blin, (float*)d_out, M);
}

// round 13
// speedup vs baseline: 1.0173x; 1.0173x over previous
#include <cuda_runtime.h>
#include <cuda_fp16.h>
#include <cuda_bf16.h>

#define NN 50000
#define EE 800000
#define DD 128
#define OO 64
#define LL 3

// ---------------- scratch (device globals) ----------------
__device__ __half g_hx[NN * DD];      // x converted to fp16
__device__ __half g_h0[NN * DD];
__device__ __half g_h1[NN * DD];
__device__ __half g_agg0[NN * DD];    // (1-a)/deg * sum_{src->dst}
__device__ __half g_agg1[NN * DD];    // a/deg * sum_{dst->src}
__device__ __half g_hmax[NN * DD];
__device__ __half g_Wt[LL * 3 * DD * DD];   // layer weights fp16, [mat][n][k]
__device__ __half g_Wlt[OO * DD];           // Wlin fp16, [n][k]

__device__ int g_deg[2 * NN];         // [0]=by dst, [1]=by src
__device__ int g_rp0[NN + 1];
__device__ int g_rp1[NN + 1];
__device__ int g_cur0[NN];
__device__ int g_cur1[NN];
__device__ int g_col0[EE];            // CSR by dst, values = src
__device__ int g_col1[EE];            // CSR by src, values = dst

// ---------------- cp.async helper ----------------
__device__ __forceinline__ void cp16(__half* s, const void* g, bool v) {
    unsigned sa = (unsigned)__cvta_generic_to_shared(s);
    int sz = v ? 16 : 0;
    asm volatile("cp.async.ca.shared.global [%0], [%1], 16, %2;"
                 :: "r"(sa), "l"(g), "r"(sz));
}

// ---------------- CSR build ----------------
__global__ void count_kernel(const int* __restrict__ ei, int E) {
    int e = blockIdx.x * blockDim.x + threadIdx.x;
    if (e >= E) return;
    int src = ei[e];
    int dst = ei[E + e];
    atomicAdd(&g_deg[dst], 1);
    atomicAdd(&g_deg[NN + src], 1);
}

__global__ void scan_kernel(int n) {
    const int* deg = g_deg + blockIdx.x * NN;
    int* rp = (blockIdx.x == 0) ? g_rp0 : g_rp1;
    int* cur = (blockIdx.x == 0) ? g_cur0 : g_cur1;

    __shared__ int sums[1024];
    int t = threadIdx.x;
    int chunk = (n + 1023) / 1024;
    int begin = t * chunk;
    int end = min(begin + chunk, n);
    int s = 0;
    for (int i = begin; i < end; i++) s += deg[i];
    sums[t] = s;
    __syncthreads();
    for (int off = 1; off < 1024; off <<= 1) {
        int v = (t >= off) ? sums[t - off] : 0;
        __syncthreads();
        sums[t] += v;
        __syncthreads();
    }
    int prefix = (t == 0) ? 0 : sums[t - 1];
    for (int i = begin; i < end; i++) {
        rp[i] = prefix;
        cur[i] = prefix;
        prefix += deg[i];
    }
    if (t == 1023) rp[n] = prefix;
}

// fused: CSR fill | x->fp16 convert | weight transpose+convert
__global__ void fill_convert_prep_kernel(
    const int* __restrict__ ei, int E,
    const float* __restrict__ x, int total4,
    const float* __restrict__ Wself, const float* __restrict__ Wstd,
    const float* __restrict__ Wdts, const float* __restrict__ Wlin,
    int fillBlocks, int convBlocks)
{
    int b = blockIdx.x;
    if (b < fillBlocks) {
        int e = b * blockDim.x + threadIdx.x;
        if (e >= E) return;
        int src = ei[e];
        int dst = ei[E + e];
        int p0 = atomicAdd(&g_cur0[dst], 1);
        g_col0[p0] = src;
        int p1 = atomicAdd(&g_cur1[src], 1);
        g_col1[p1] = dst;
    } else if (b < fillBlocks + convBlocks) {
        int i = (b - fillBlocks) * blockDim.x + threadIdx.x;
        if (i >= total4) return;
        float4 v = ((const float4*)x)[i];
        __half2 h0 = __floats2half2_rn(v.x, v.y);
        __half2 h1 = __floats2half2_rn(v.z, v.w);
        uint2 u;
        u.x = *(unsigned*)&h0;
        u.y = *(unsigned*)&h1;
        ((uint2*)g_hx)[i] = u;
    } else {
        int idx = (b - fillBlocks - convBlocks) * blockDim.x + threadIdx.x;
        if (idx < LL * 3 * DD * DD) {
            int mat = idx >> 14;
            int r = (idx >> 7) & 127;
            int c = idx & 127;
            int l = mat / 3, s = mat % 3;
            const float* W = (s == 0) ? Wself : (s == 1) ? Wstd : Wdts;
            float v = W[(size_t)l * DD * DD + r * DD + c];
            g_Wt[(size_t)mat * DD * DD + c * DD + r] = __float2half(v);
        } else {
            int i2 = idx - LL * 3 * DD * DD;
            if (i2 < OO * DD) {
                int n = i2 >> 7;
                int k = i2 & 127;
                g_Wlt[n * DD + k] = __float2half(Wlin[k * OO + n]);
            }
        }
    }
}

// ---------------- aggregation: warp per node, 16 lanes x uint4 -------------
// lanes 0-15 process even neighbors, 16-31 odd; shfl_xor(16) combine.
__device__ __forceinline__ __half2 u2h(unsigned u) { return *(__half2*)&u; }

__global__ void agg_kernel(const __half* __restrict__ h,
                           const float* __restrict__ alpha, int M) {
    int gw = (blockIdx.x * blockDim.x + threadIdx.x) >> 5;
    if (gw >= M) return;
    int lane = threadIdx.x & 31;
    int half_id = lane >> 4;     // 0 or 1
    int base = (lane & 15) * 8;  // 8 halves per lane
    float a = alpha[0];

    #pragma unroll
    for (int dir = 0; dir < 2; dir++) {
        const int* rp  = dir ? g_rp1  : g_rp0;
        const int* col = dir ? g_col1 : g_col0;
        __half* out    = dir ? g_agg1 : g_agg0;
        float coef     = dir ? a : (1.f - a);

        int s = rp[gw], e = rp[gw + 1];
        float accf[8] = { 0.f, 0.f, 0.f, 0.f, 0.f, 0.f, 0.f, 0.f };
        int i = s;
        for (; i + 7 < e; i += 8) {
            uint4 v0 = *(const uint4*)(h + (size_t)col[i + 0 + half_id] * DD + base);
            uint4 v1 = *(const uint4*)(h + (size_t)col[i + 2 + half_id] * DD + base);
            uint4 v2 = *(const uint4*)(h + (size_t)col[i + 4 + half_id] * DD + base);
            uint4 v3 = *(const uint4*)(h + (size_t)col[i + 6 + half_id] * DD + base);
            __half2 t0 = __hadd2(__hadd2(u2h(v0.x), u2h(v1.x)), __hadd2(u2h(v2.x), u2h(v3.x)));
            __half2 t1 = __hadd2(__hadd2(u2h(v0.y), u2h(v1.y)), __hadd2(u2h(v2.y), u2h(v3.y)));
            __half2 t2 = __hadd2(__hadd2(u2h(v0.z), u2h(v1.z)), __hadd2(u2h(v2.z), u2h(v3.z)));
            __half2 t3 = __hadd2(__hadd2(u2h(v0.w), u2h(v1.w)), __hadd2(u2h(v2.w), u2h(v3.w)));
            float2 f;
            f = __half22float2(t0); accf[0] += f.x; accf[1] += f.y;
            f = __half22float2(t1); accf[2] += f.x; accf[3] += f.y;
            f = __half22float2(t2); accf[4] += f.x; accf[5] += f.y;
            f = __half22float2(t3); accf[6] += f.x; accf[7] += f.y;
        }
        for (; i + 1 < e; i += 2) {
            uint4 v0 = *(const uint4*)(h + (size_t)col[i + half_id] * DD + base);
            float2 f;
            f = __half22float2(u2h(v0.x)); accf[0] += f.x; accf[1] += f.y;
            f = __half22float2(u2h(v0.y)); accf[2] += f.x; accf[3] += f.y;
            f = __half22float2(u2h(v0.z)); accf[4] += f.x; accf[5] += f.y;
            f = __half22float2(u2h(v0.w)); accf[6] += f.x; accf[7] += f.y;
        }
        if (i < e && half_id == 0) {
            uint4 v0 = *(const uint4*)(h + (size_t)col[i] * DD + base);
            float2 f;
            f = __half22float2(u2h(v0.x)); accf[0] += f.x; accf[1] += f.y;
            f = __half22float2(u2h(v0.y)); accf[2] += f.x; accf[3] += f.y;
            f = __half22float2(u2h(v0.z)); accf[4] += f.x; accf[5] += f.y;
            f = __half22float2(u2h(v0.w)); accf[6] += f.x; accf[7] += f.y;
        }
        // combine the two half-warps
        #pragma unroll
        for (int j = 0; j < 8; j++)
            accf[j] += __shfl_xor_sync(0xFFFFFFFFu, accf[j], 16);

        if (half_id == 0) {
            float sc = coef / fmaxf((float)(e - s), 1.f);
            __half2 o[4];
            o[0] = __floats2half2_rn(accf[0] * sc, accf[1] * sc);
            o[1] = __floats2half2_rn(accf[2] * sc, accf[3] * sc);
            o[2] = __floats2half2_rn(accf[4] * sc, accf[5] * sc);
            o[3] = __floats2half2_rn(accf[6] * sc, accf[7] * sc);
            *(uint4*)(out + (size_t)gw * DD + base) = *(uint4*)o;
        }
    }
}

// ---------------- fp16 tensor-core layer GEMM (cp.async, BK=32) ------------
#define SA 40   // smem row stride in halves

__global__ __launch_bounds__(256) void gemm_layer_f16(
    const __half* __restrict__ A0,
    const __half* __restrict__ Wt,   // layer base (3 mats)
    const float* __restrict__ bs0,
    const float* __restrict__ bs1,
    const float* __restrict__ bs2,
    const float* __restrict__ alpha,
    __half* __restrict__ Hout,
    int firstLayer, int M)
{
    __shared__ __align__(16) __half As[2][128 * SA];
    __shared__ __align__(16) __half Bs[2][128 * SA];
    __shared__ float bias_s[DD];

    int tid = threadIdx.x;
    int block_row = blockIdx.x * 128;
    int warpId = tid >> 5;
    int lane = tid & 31;
    int g = lane >> 2;
    int t = lane & 3;
    int warp_row = warpId & 3;
    int warp_col = warpId >> 2;

    if (tid < DD) {
        float a = alpha[0];
        bias_s[tid] = bs0[tid] + (1.f - a) * bs1[tid] + a * bs2[tid];
    }

    float acc[2][8][4];
    #pragma unroll
    for (int mt = 0; mt < 2; mt++)
        #pragma unroll
        for (int nt = 0; nt < 8; nt++)
            #pragma unroll
            for (int r = 0; r < 4; r++) acc[mt][nt][r] = 0.f;

    const __half* Aseg[3] = { A0, g_agg0, g_agg1 };

    int l_row = tid >> 2;          // 0..63
    int l_kq = (tid & 3) * 8;      // halves: 0,8,16,24

    auto cp_chunk = [&](int c, int buf) {
        int seg = c >> 2;
        int kl = (c & 3) * 32;
        const __half* A = Aseg[seg];
        const __half* B = Wt + (size_t)seg * DD * DD;
        #pragma unroll
        for (int j = 0; j < 2; j++) {
            int row = l_row + j * 64;
            int gr = block_row + row;
            cp16(&As[buf][row * SA + l_kq], A + (size_t)gr * DD + kl + l_kq, gr < M);
            cp16(&Bs[buf][row * SA + l_kq], B + (size_t)row * DD + kl + l_kq, true);
        }
        asm volatile("cp.async.commit_group;");
    };

    cp_chunk(0, 0);

    #pragma unroll 1
    for (int c = 0; c < 12; c++) {
        int buf = c & 1;
        if (c < 11) {
            cp_chunk(c + 1, buf ^ 1);
            asm volatile("cp.async.wait_group 1;");
        } else {
            asm volatile("cp.async.wait_group 0;");
        }
        __syncthreads();

        #pragma unroll
        for (int ks = 0; ks < 2; ks++) {
            int k0 = ks * 16;
            unsigned af[2][4];
            #pragma unroll
            for (int mt = 0; mt < 2; mt++) {
                int mrow = warp_row * 32 + mt * 16;
                const __half* base = &As[buf][0];
                af[mt][0] = *(const unsigned*)&base[(mrow + g) * SA + k0 + 2 * t];
                af[mt][1] = *(const unsigned*)&base[(mrow + g + 8) * SA + k0 + 2 * t];
                af[mt][2] = *(const unsigned*)&base[(mrow + g) * SA + k0 + 8 + 2 * t];
                af[mt][3] = *(const unsigned*)&base[(mrow + g + 8) * SA + k0 + 8 + 2 * t];
            }
            unsigned bf[8][2];
            #pragma unroll
            for (int nt = 0; nt < 8; nt++) {
                int n = warp_col * 64 + nt * 8 + g;
                const __half* base = &Bs[buf][0];
                bf[nt][0] = *(const unsigned*)&base[n * SA + k0 + 2 * t];
                bf[nt][1] = *(const unsigned*)&base[n * SA + k0 + 8 + 2 * t];
            }
            #pragma unroll
            for (int mt = 0; mt < 2; mt++)
                #pragma unroll
                for (int nt = 0; nt < 8; nt++) {
                    asm volatile(
                        "mma.sync.aligned.m16n8k16.row.col.f32.f16.f16.f32 "
                        "{%0,%1,%2,%3}, {%4,%5,%6,%7}, {%8,%9}, {%0,%1,%2,%3};"
                        : "+f"(acc[mt][nt][0]), "+f"(acc[mt][nt][1]),
                          "+f"(acc[mt][nt][2]), "+f"(acc[mt][nt][3])
                        : "r"(af[mt][0]), "r"(af[mt][1]), "r"(af[mt][2]), "r"(af[mt][3]),
                          "r"(bf[nt][0]), "r"(bf[nt][1]));
                }
        }
        __syncthreads();
    }

    // epilogue: bias + relu + store h(fp16) + JK max(fp16)
    #pragma unroll
    for (int mt = 0; mt < 2; mt++) {
        #pragma unroll
        for (int nt = 0; nt < 8; nt++) {
            int c0 = warp_col * 64 + nt * 8 + 2 * t;
            float b0v = bias_s[c0];
            float b1v = bias_s[c0 + 1];
            #pragma unroll
            for (int rr = 0; rr < 2; rr++) {
                int r = block_row + warp_row * 32 + mt * 16 + g + rr * 8;
                if (r < M) {
                    float v0 = fmaxf(acc[mt][nt][rr * 2 + 0] + b0v, 0.f);
                    float v1 = fmaxf(acc[mt][nt][rr * 2 + 1] + b1v, 0.f);
                    __half2 hv = __floats2half2_rn(v0, v1);
                    *(__half2*)(Hout + (size_t)r * DD + c0) = hv;
                    __half2* mp = (__half2*)(g_hmax + (size_t)r * DD + c0);
                    if (firstLayer) {
                        *mp = hv;
                    } else {
                        *mp = __hmax2(*mp, hv);
                    }
                }
            }
        }
    }
}

// ---------------- final linear via fp16 MMA: hmax @ Wlt^T + blin ------------
#define SF 136

__global__ __launch_bounds__(256) void final_mma_kernel(
    const float* __restrict__ blin, float* __restrict__ out, int M)
{
    extern __shared__ char dynsm[];
    float* bias_s = (float*)dynsm;
    __half* As = (__half*)(dynsm + 256);
    __half* Bs = As + 128 * SF;

    int tid = threadIdx.x;
    int block_row = blockIdx.x * 128;
    int warpId = tid >> 5;
    int lane = tid & 31;
    int g = lane >> 2;
    int t = lane & 3;
    int warp_row = warpId & 3;
    int warp_col = warpId >> 2;

    if (tid < OO) bias_s[tid] = blin[tid];

    #pragma unroll
    for (int k = 0; k < 8; k++) {
        int idx = tid + k * 256;
        int row = idx >> 4;
        int q = (idx & 15) * 8;
        int gr = block_row + row;
        uint4 v = make_uint4(0u, 0u, 0u, 0u);
        if (gr < M) v = *(const uint4*)(g_hmax + (size_t)gr * DD + q);
        *(uint4*)&As[row * SF + q] = v;
    }
    #pragma unroll
    for (int k = 0; k < 4; k++) {
        int idx = tid + k * 256;
        int row = idx >> 4;
        int q = (idx & 15) * 8;
        *(uint4*)&Bs[row * SF + q] = *(const uint4*)(g_Wlt + row * DD + q);
    }
    __syncthreads();

    float acc[2][4][4];
    #pragma unroll
    for (int mt = 0; mt < 2; mt++)
        #pragma unroll
        for (int nt = 0; nt < 4; nt++)
            #pragma unroll
            for (int r = 0; r < 4; r++) acc[mt][nt][r] = 0.f;

    #pragma unroll
    for (int kc = 0; kc < 8; kc++) {
        int k0 = kc * 16;
        unsigned af[2][4];
        #pragma unroll
        for (int mt = 0; mt < 2; mt++) {
            int mrow = warp_row * 32 + mt * 16;
            af[mt][0] = *(const unsigned*)&As[(mrow + g) * SF + k0 + 2 * t];
            af[mt][1] = *(const unsigned*)&As[(mrow + g + 8) * SF + k0 + 2 * t];
            af[mt][2] = *(const unsigned*)&As[(mrow + g) * SF + k0 + 8 + 2 * t];
            af[mt][3] = *(const unsigned*)&As[(mrow + g + 8) * SF + k0 + 8 + 2 * t];
        }
        unsigned bf[4][2];
        #pragma unroll
        for (int nt = 0; nt < 4; nt++) {
            int n = warp_col * 32 + nt * 8 + g;
            bf[nt][0] = *(const unsigned*)&Bs[n * SF + k0 + 2 * t];
            bf[nt][1] = *(const unsigned*)&Bs[n * SF + k0 + 8 + 2 * t];
        }
        #pragma unroll
        for (int mt = 0; mt < 2; mt++)
            #pragma unroll
            for (int nt = 0; nt < 4; nt++) {
                asm volatile(
                    "mma.sync.aligned.m16n8k16.row.col.f32.f16.f16.f32 "
                    "{%0,%1,%2,%3}, {%4,%5,%6,%7}, {%8,%9}, {%0,%1,%2,%3};"
                    : "+f"(acc[mt][nt][0]), "+f"(acc[mt][nt][1]),
                      "+f"(acc[mt][nt][2]), "+f"(acc[mt][nt][3])
                    : "r"(af[mt][0]), "r"(af[mt][1]), "r"(af[mt][2]), "r"(af[mt][3]),
                      "r"(bf[nt][0]), "r"(bf[nt][1]));
            }
    }

    #pragma unroll
    for (int mt = 0; mt < 2; mt++) {
        #pragma unroll
        for (int nt = 0; nt < 4; nt++) {
            int c0 = warp_col * 32 + nt * 8 + 2 * t;
            float b0v = bias_s[c0];
            float b1v = bias_s[c0 + 1];
            #pragma unroll
            for (int rr = 0; rr < 2; rr++) {
                int r = block_row + warp_row * 32 + mt * 16 + g + rr * 8;
                if (r < M) {
                    float2 o;
                    o.x = acc[mt][nt][rr * 2 + 0] + b0v;
                    o.y = acc[mt][nt][rr * 2 + 1] + b1v;
                    *(float2*)(out + (size_t)r * OO + c0) = o;
                }
            }
        }
    }
}

// ---------------- launch ----------------
extern "C" void kernel_launch(void* const* d_in, const int* in_sizes, int n_in,
                              void* d_out, int out_size) {
    const float* x     = (const float*)d_in[0];
    const int*   ei    = (const int*)d_in[1];
    const float* Wself = (const float*)d_in[2];
    const float* bself = (const float*)d_in[3];
    const float* Wstd  = (const float*)d_in[4];
    const float* bstd  = (const float*)d_in[5];
    const float* Wdts  = (const float*)d_in[6];
    const float* bdts  = (const float*)d_in[7];
    const float* Wlin  = (const float*)d_in[8];
    const float* blin  = (const float*)d_in[9];
    const float* alpha = (const float*)d_in[10];

    int M = in_sizes[0] / DD;        // 50000
    int E = in_sizes[1] / 2;         // 800000

    __half* hx; cudaGetSymbolAddress((void**)&hx, g_hx);
    __half* h0; cudaGetSymbolAddress((void**)&h0, g_h0);
    __half* h1; cudaGetSymbolAddress((void**)&h1, g_h1);
    __half* wt; cudaGetSymbolAddress((void**)&wt, g_Wt);
    int* degp; cudaGetSymbolAddress((void**)&degp, g_deg);

    const int FINAL_SMEM = 256 + (128 * SF + 64 * SF) * 2;   // 52480
    cudaFuncSetAttribute(final_mma_kernel,
                         cudaFuncAttributeMaxDynamicSharedMemorySize, FINAL_SMEM);

    cudaMemsetAsync(degp, 0, 2 * NN * sizeof(int));

    count_kernel<<<(E + 255) / 256, 256>>>(ei, E);
    scan_kernel<<<2, 1024>>>(M);
    int total4 = M * DD / 4;
    int fillBlocks = (E + 255) / 256;
    int convBlocks = (total4 + 255) / 256;
    int prepBlocks = (LL * 3 * DD * DD + OO * DD + 255) / 256;
    fill_convert_prep_kernel<<<fillBlocks + convBlocks + prepBlocks, 256>>>(
        ei, E, x, total4, Wself, Wstd, Wdts, Wlin, fillBlocks, convBlocks);

    // layers
    const __half* cur = hx;
    __half* bufs[2] = { h0, h1 };
    int gemm_grid = (M + 127) / 128;
    int agg_grid = (M * 32 + 255) / 256;
    for (int l = 0; l < LL; l++) {
        agg_kernel<<<agg_grid, 256>>>(cur, alpha, M);
        __half* outb = bufs[l & 1];
        gemm_layer_f16<<<gemm_grid, 256>>>(
            cur,
            wt + (size_t)l * 3 * DD * DD,
            bself + (size_t)l * DD,
            bstd  + (size_t)l * DD,
            bdts  + (size_t)l * DD,
            alpha, outb, (l == 0) ? 1 : 0, M);
        cur = outb;
    }

    // final linear (fp16 MMA)
    final_mma_kernel<<<(M + 127) / 128, 256, FINAL_SMEM>>>(blin, (float*)d_out, M);
}

// round 14
// speedup vs baseline: 1.0568x; 1.0388x over previous
#include <cuda_runtime.h>
#include <cuda_fp16.h>
#include <cuda_bf16.h>

#define NN 50000
#define EE 800000
#define DD 128
#define OO 64
#define LL 3

// ---------------- scratch (device globals) ----------------
__device__ __half g_hx[NN * DD];      // x converted to fp16
__device__ __half g_h0[NN * DD];      // h2 buffer
__device__ __half g_agg0[NN * DD];    // (1-a)/deg * sum_{src->dst}
__device__ __half g_agg1[NN * DD];    // a/deg * sum_{dst->src}
__device__ __half g_hmax[NN * DD];    // JK max (h1 lives here after layer 0)
__device__ __half g_Wt[LL * 3 * DD * DD];   // layer weights fp16, [mat][n][k]
__device__ __half g_Wlt[OO * DD];           // Wlin fp16, [n][k]

__device__ int g_deg[2 * NN];         // [0]=by dst, [1]=by src
__device__ int g_rp0[NN + 1];
__device__ int g_rp1[NN + 1];
__device__ int g_cur0[NN];
__device__ int g_cur1[NN];
__device__ int g_col0[EE];            // CSR by dst, values = src
__device__ int g_col1[EE];            // CSR by src, values = dst

// ---------------- cp.async helper ----------------
__device__ __forceinline__ void cp16(__half* s, const void* g, bool v) {
    unsigned sa = (unsigned)__cvta_generic_to_shared(s);
    int sz = v ? 16 : 0;
    asm volatile("cp.async.ca.shared.global [%0], [%1], 16, %2;"
                 :: "r"(sa), "l"(g), "r"(sz));
}

// ---------------- CSR build ----------------
__global__ void count_kernel(const int* __restrict__ ei, int E) {
    int e = blockIdx.x * blockDim.x + threadIdx.x;
    if (e >= E) return;
    int src = ei[e];
    int dst = ei[E + e];
    atomicAdd(&g_deg[dst], 1);
    atomicAdd(&g_deg[NN + src], 1);
}

__global__ void scan_kernel(int n) {
    const int* deg = g_deg + blockIdx.x * NN;
    int* rp = (blockIdx.x == 0) ? g_rp0 : g_rp1;
    int* cur = (blockIdx.x == 0) ? g_cur0 : g_cur1;

    __shared__ int sums[1024];
    int t = threadIdx.x;
    int chunk = (n + 1023) / 1024;
    int begin = t * chunk;
    int end = min(begin + chunk, n);
    int s = 0;
    for (int i = begin; i < end; i++) s += deg[i];
    sums[t] = s;
    __syncthreads();
    for (int off = 1; off < 1024; off <<= 1) {
        int v = (t >= off) ? sums[t - off] : 0;
        __syncthreads();
        sums[t] += v;
        __syncthreads();
    }
    int prefix = (t == 0) ? 0 : sums[t - 1];
    for (int i = begin; i < end; i++) {
        rp[i] = prefix;
        cur[i] = prefix;
        prefix += deg[i];
    }
    if (t == 1023) rp[n] = prefix;
}

// fused: CSR fill | x->fp16 convert | weight transpose+convert
__global__ void fill_convert_prep_kernel(
    const int* __restrict__ ei, int E,
    const float* __restrict__ x, int total4,
    const float* __restrict__ Wself, const float* __restrict__ Wstd,
    const float* __restrict__ Wdts, const float* __restrict__ Wlin,
    int fillBlocks, int convBlocks)
{
    int b = blockIdx.x;
    if (b < fillBlocks) {
        int e = b * blockDim.x + threadIdx.x;
        if (e >= E) return;
        int src = ei[e];
        int dst = ei[E + e];
        int p0 = atomicAdd(&g_cur0[dst], 1);
        g_col0[p0] = src;
        int p1 = atomicAdd(&g_cur1[src], 1);
        g_col1[p1] = dst;
    } else if (b < fillBlocks + convBlocks) {
        int i = (b - fillBlocks) * blockDim.x + threadIdx.x;
        if (i >= total4) return;
        float4 v = ((const float4*)x)[i];
        __half2 h0 = __floats2half2_rn(v.x, v.y);
        __half2 h1 = __floats2half2_rn(v.z, v.w);
        uint2 u;
        u.x = *(unsigned*)&h0;
        u.y = *(unsigned*)&h1;
        ((uint2*)g_hx)[i] = u;
    } else {
        int idx = (b - fillBlocks - convBlocks) * blockDim.x + threadIdx.x;
        if (idx < LL * 3 * DD * DD) {
            int mat = idx >> 14;
            int r = (idx >> 7) & 127;
            int c = idx & 127;
            int l = mat / 3, s = mat % 3;
            const float* W = (s == 0) ? Wself : (s == 1) ? Wstd : Wdts;
            float v = W[(size_t)l * DD * DD + r * DD + c];
            g_Wt[(size_t)mat * DD * DD + c * DD + r] = __float2half(v);
        } else {
            int i2 = idx - LL * 3 * DD * DD;
            if (i2 < OO * DD) {
                int n = i2 >> 7;
                int k = i2 & 127;
                g_Wlt[n * DD + k] = __float2half(Wlin[k * OO + n]);
            }
        }
    }
}

// ---------------- aggregation: one warp per node, 4-deep fp16 tree ---------
__device__ __forceinline__ __half2 u2h(unsigned u) { return *(__half2*)&u; }

__global__ void agg_kernel(const __half* __restrict__ h,
                           const float* __restrict__ alpha, int M) {
    int gw = (blockIdx.x * blockDim.x + threadIdx.x) >> 5;
    if (gw >= M) return;
    int lane = threadIdx.x & 31;
    int base = lane * 4;   // halves
    float a = alpha[0];

    #pragma unroll
    for (int dir = 0; dir < 2; dir++) {
        const int* rp  = dir ? g_rp1  : g_rp0;
        const int* col = dir ? g_col1 : g_col0;
        __half* out    = dir ? g_agg1 : g_agg0;
        float coef     = dir ? a : (1.f - a);

        int s = rp[gw], e = rp[gw + 1];
        float4 acc = make_float4(0.f, 0.f, 0.f, 0.f);
        int i = s;
        for (; i + 3 < e; i += 4) {
            int n0 = col[i],     n1 = col[i + 1];
            int n2 = col[i + 2], n3 = col[i + 3];
            uint2 u0 = *(const uint2*)(h + (size_t)n0 * DD + base);
            uint2 u1 = *(const uint2*)(h + (size_t)n1 * DD + base);
            uint2 u2 = *(const uint2*)(h + (size_t)n2 * DD + base);
            uint2 u3 = *(const uint2*)(h + (size_t)n3 * DD + base);
            __half2 s0 = __hadd2(__hadd2(u2h(u0.x), u2h(u1.x)),
                                 __hadd2(u2h(u2.x), u2h(u3.x)));
            __half2 s1 = __hadd2(__hadd2(u2h(u0.y), u2h(u1.y)),
                                 __hadd2(u2h(u2.y), u2h(u3.y)));
            float2 f0 = __half22float2(s0);
            float2 f1 = __half22float2(s1);
            acc.x += f0.x; acc.y += f0.y;
            acc.z += f1.x; acc.w += f1.y;
        }
        for (; i < e; i++) {
            int n0 = col[i];
            uint2 u0 = *(const uint2*)(h + (size_t)n0 * DD + base);
            float2 f0 = __half22float2(u2h(u0.x));
            float2 f1 = __half22float2(u2h(u0.y));
            acc.x += f0.x; acc.y += f0.y;
            acc.z += f1.x; acc.w += f1.y;
        }
        float sc = coef / fmaxf((float)(e - s), 1.f);
        __half2 o0 = __floats2half2_rn(acc.x * sc, acc.y * sc);
        __half2 o1 = __floats2half2_rn(acc.z * sc, acc.w * sc);
        uint2 u;
        u.x = *(unsigned*)&o0;
        u.y = *(unsigned*)&o1;
        *(uint2*)(out + (size_t)gw * DD + base) = u;
    }
}

// ---------------- fp16 tensor-core layer GEMM (cp.async, BK=32) ------------
// mode: 0 = layer0 (write hmax only), 1 = mid layer (write Hout + max hmax),
//       2 = last layer (max hmax only)
#define SA 40   // smem row stride in halves

__global__ __launch_bounds__(256) void gemm_layer_f16(
    const __half* __restrict__ A0,
    const __half* __restrict__ Wt,   // layer base (3 mats)
    const float* __restrict__ bs0,
    const float* __restrict__ bs1,
    const float* __restrict__ bs2,
    const float* __restrict__ alpha,
    __half* __restrict__ Hout,
    int mode, int M)
{
    __shared__ __align__(16) __half As[2][128 * SA];
    __shared__ __align__(16) __half Bs[2][128 * SA];
    __shared__ float bias_s[DD];

    int tid = threadIdx.x;
    int block_row = blockIdx.x * 128;
    int warpId = tid >> 5;
    int lane = tid & 31;
    int g = lane >> 2;
    int t = lane & 3;
    int warp_row = warpId & 3;
    int warp_col = warpId >> 2;

    if (tid < DD) {
        float a = alpha[0];
        bias_s[tid] = bs0[tid] + (1.f - a) * bs1[tid] + a * bs2[tid];
    }

    float acc[2][8][4];
    #pragma unroll
    for (int mt = 0; mt < 2; mt++)
        #pragma unroll
        for (int nt = 0; nt < 8; nt++)
            #pragma unroll
            for (int r = 0; r < 4; r++) acc[mt][nt][r] = 0.f;

    const __half* Aseg[3] = { A0, g_agg0, g_agg1 };

    int l_row = tid >> 2;          // 0..63
    int l_kq = (tid & 3) * 8;      // halves: 0,8,16,24

    auto cp_chunk = [&](int c, int buf) {
        int seg = c >> 2;
        int kl = (c & 3) * 32;
        const __half* A = Aseg[seg];
        const __half* B = Wt + (size_t)seg * DD * DD;
        #pragma unroll
        for (int j = 0; j < 2; j++) {
            int row = l_row + j * 64;
            int gr = block_row + row;
            cp16(&As[buf][row * SA + l_kq], A + (size_t)gr * DD + kl + l_kq, gr < M);
            cp16(&Bs[buf][row * SA + l_kq], B + (size_t)row * DD + kl + l_kq, true);
        }
        asm volatile("cp.async.commit_group;");
    };

    cp_chunk(0, 0);

    #pragma unroll 1
    for (int c = 0; c < 12; c++) {
        int buf = c & 1;
        if (c < 11) {
            cp_chunk(c + 1, buf ^ 1);
            asm volatile("cp.async.wait_group 1;");
        } else {
            asm volatile("cp.async.wait_group 0;");
        }
        __syncthreads();

        #pragma unroll
        for (int ks = 0; ks < 2; ks++) {
            int k0 = ks * 16;
            unsigned af[2][4];
            #pragma unroll
            for (int mt = 0; mt < 2; mt++) {
                int mrow = warp_row * 32 + mt * 16;
                const __half* base = &As[buf][0];
                af[mt][0] = *(const unsigned*)&base[(mrow + g) * SA + k0 + 2 * t];
                af[mt][1] = *(const unsigned*)&base[(mrow + g + 8) * SA + k0 + 2 * t];
                af[mt][2] = *(const unsigned*)&base[(mrow + g) * SA + k0 + 8 + 2 * t];
                af[mt][3] = *(const unsigned*)&base[(mrow + g + 8) * SA + k0 + 8 + 2 * t];
            }
            unsigned bf[8][2];
            #pragma unroll
            for (int nt = 0; nt < 8; nt++) {
                int n = warp_col * 64 + nt * 8 + g;
                const __half* base = &Bs[buf][0];
                bf[nt][0] = *(const unsigned*)&base[n * SA + k0 + 2 * t];
                bf[nt][1] = *(const unsigned*)&base[n * SA + k0 + 8 + 2 * t];
            }
            #pragma unroll
            for (int mt = 0; mt < 2; mt++)
                #pragma unroll
                for (int nt = 0; nt < 8; nt++) {
                    asm volatile(
                        "mma.sync.aligned.m16n8k16.row.col.f32.f16.f16.f32 "
                        "{%0,%1,%2,%3}, {%4,%5,%6,%7}, {%8,%9}, {%0,%1,%2,%3};"
                        : "+f"(acc[mt][nt][0]), "+f"(acc[mt][nt][1]),
                          "+f"(acc[mt][nt][2]), "+f"(acc[mt][nt][3])
                        : "r"(af[mt][0]), "r"(af[mt][1]), "r"(af[mt][2]), "r"(af[mt][3]),
                          "r"(bf[nt][0]), "r"(bf[nt][1]));
                }
        }
        __syncthreads();
    }

    // epilogue: bias + relu; store per mode
    #pragma unroll
    for (int mt = 0; mt < 2; mt++) {
        #pragma unroll
        for (int nt = 0; nt < 8; nt++) {
            int c0 = warp_col * 64 + nt * 8 + 2 * t;
            float b0v = bias_s[c0];
            float b1v = bias_s[c0 + 1];
            #pragma unroll
            for (int rr = 0; rr < 2; rr++) {
                int r = block_row + warp_row * 32 + mt * 16 + g + rr * 8;
                if (r < M) {
                    float v0 = fmaxf(acc[mt][nt][rr * 2 + 0] + b0v, 0.f);
                    float v1 = fmaxf(acc[mt][nt][rr * 2 + 1] + b1v, 0.f);
                    __half2 hv = __floats2half2_rn(v0, v1);
                    __half2* mp = (__half2*)(g_hmax + (size_t)r * DD + c0);
                    if (mode == 0) {
                        *mp = hv;                 // h1 lives in hmax
                    } else {
                        if (mode == 1)
                            *(__half2*)(Hout + (size_t)r * DD + c0) = hv;
                        *mp = __hmax2(*mp, hv);
                    }
                }
            }
        }
    }
}

// ---------------- final linear via fp16 MMA: hmax @ Wlt^T + blin ------------
#define SF 136

__global__ __launch_bounds__(256) void final_mma_kernel(
    const float* __restrict__ blin, float* __restrict__ out, int M)
{
    extern __shared__ char dynsm[];
    float* bias_s = (float*)dynsm;
    __half* As = (__half*)(dynsm + 256);
    __half* Bs = As + 128 * SF;

    int tid = threadIdx.x;
    int block_row = blockIdx.x * 128;
    int warpId = tid >> 5;
    int lane = tid & 31;
    int g = lane >> 2;
    int t = lane & 3;
    int warp_row = warpId & 3;
    int warp_col = warpId >> 2;

    if (tid < OO) bias_s[tid] = blin[tid];

    #pragma unroll
    for (int k = 0; k < 8; k++) {
        int idx = tid + k * 256;
        int row = idx >> 4;
        int q = (idx & 15) * 8;
        int gr = block_row + row;
        uint4 v = make_uint4(0u, 0u, 0u, 0u);
        if (gr < M) v = *(const uint4*)(g_hmax + (size_t)gr * DD + q);
        *(uint4*)&As[row * SF + q] = v;
    }
    #pragma unroll
    for (int k = 0; k < 4; k++) {
        int idx = tid + k * 256;
        int row = idx >> 4;
        int q = (idx & 15) * 8;
        *(uint4*)&Bs[row * SF + q] = *(const uint4*)(g_Wlt + row * DD + q);
    }
    __syncthreads();

    float acc[2][4][4];
    #pragma unroll
    for (int mt = 0; mt < 2; mt++)
        #pragma unroll
        for (int nt = 0; nt < 4; nt++)
            #pragma unroll
            for (int r = 0; r < 4; r++) acc[mt][nt][r] = 0.f;

    #pragma unroll
    for (int kc = 0; kc < 8; kc++) {
        int k0 = kc * 16;
        unsigned af[2][4];
        #pragma unroll
        for (int mt = 0; mt < 2; mt++) {
            int mrow = warp_row * 32 + mt * 16;
            af[mt][0] = *(const unsigned*)&As[(mrow + g) * SF + k0 + 2 * t];
            af[mt][1] = *(const unsigned*)&As[(mrow + g + 8) * SF + k0 + 2 * t];
            af[mt][2] = *(const unsigned*)&As[(mrow + g) * SF + k0 + 8 + 2 * t];
            af[mt][3] = *(const unsigned*)&As[(mrow + g + 8) * SF + k0 + 8 + 2 * t];
        }
        unsigned bf[4][2];
        #pragma unroll
        for (int nt = 0; nt < 4; nt++) {
            int n = warp_col * 32 + nt * 8 + g;
            bf[nt][0] = *(const unsigned*)&Bs[n * SF + k0 + 2 * t];
            bf[nt][1] = *(const unsigned*)&Bs[n * SF + k0 + 8 + 2 * t];
        }
        #pragma unroll
        for (int mt = 0; mt < 2; mt++)
            #pragma unroll
            for (int nt = 0; nt < 4; nt++) {
                asm volatile(
                    "mma.sync.aligned.m16n8k16.row.col.f32.f16.f16.f32 "
                    "{%0,%1,%2,%3}, {%4,%5,%6,%7}, {%8,%9}, {%0,%1,%2,%3};"
                    : "+f"(acc[mt][nt][0]), "+f"(acc[mt][nt][1]),
                      "+f"(acc[mt][nt][2]), "+f"(acc[mt][nt][3])
                    : "r"(af[mt][0]), "r"(af[mt][1]), "r"(af[mt][2]), "r"(af[mt][3]),
                      "r"(bf[nt][0]), "r"(bf[nt][1]));
            }
    }

    #pragma unroll
    for (int mt = 0; mt < 2; mt++) {
        #pragma unroll
        for (int nt = 0; nt < 4; nt++) {
            int c0 = warp_col * 32 + nt * 8 + 2 * t;
            float b0v = bias_s[c0];
            float b1v = bias_s[c0 + 1];
            #pragma unroll
            for (int rr = 0; rr < 2; rr++) {
                int r = block_row + warp_row * 32 + mt * 16 + g + rr * 8;
                if (r < M) {
                    float2 o;
                    o.x = acc[mt][nt][rr * 2 + 0] + b0v;
                    o.y = acc[mt][nt][rr * 2 + 1] + b1v;
                    *(float2*)(out + (size_t)r * OO + c0) = o;
                }
            }
        }
    }
}

// ---------------- launch ----------------
extern "C" void kernel_launch(void* const* d_in, const int* in_sizes, int n_in,
                              void* d_out, int out_size) {
    const float* x     = (const float*)d_in[0];
    const int*   ei    = (const int*)d_in[1];
    const float* Wself = (const float*)d_in[2];
    const float* bself = (const float*)d_in[3];
    const float* Wstd  = (const float*)d_in[4];
    const float* bstd  = (const float*)d_in[5];
    const float* Wdts  = (const float*)d_in[6];
    const float* bdts  = (const float*)d_in[7];
    const float* Wlin  = (const float*)d_in[8];
    const float* blin  = (const float*)d_in[9];
    const float* alpha = (const float*)d_in[10];

    int M = in_sizes[0] / DD;        // 50000
    int E = in_sizes[1] / 2;         // 800000

    __half* hx;   cudaGetSymbolAddress((void**)&hx, g_hx);
    __half* h0;   cudaGetSymbolAddress((void**)&h0, g_h0);
    __half* hmax; cudaGetSymbolAddress((void**)&hmax, g_hmax);
    __half* wt;   cudaGetSymbolAddress((void**)&wt, g_Wt);
    int* degp;    cudaGetSymbolAddress((void**)&degp, g_deg);

    const int FINAL_SMEM = 256 + (128 * SF + 64 * SF) * 2;   // 52480
    cudaFuncSetAttribute(final_mma_kernel,
                         cudaFuncAttributeMaxDynamicSharedMemorySize, FINAL_SMEM);

    cudaMemsetAsync(degp, 0, 2 * NN * sizeof(int));

    count_kernel<<<(E + 255) / 256, 256>>>(ei, E);
    scan_kernel<<<2, 1024>>>(M);
    int total4 = M * DD / 4;
    int fillBlocks = (E + 255) / 256;
    int convBlocks = (total4 + 255) / 256;
    int prepBlocks = (LL * 3 * DD * DD + OO * DD + 255) / 256;
    fill_convert_prep_kernel<<<fillBlocks + convBlocks + prepBlocks, 256>>>(
        ei, E, x, total4, Wself, Wstd, Wdts, Wlin, fillBlocks, convBlocks);

    // layers: h1 lives in g_hmax (layer0 out, layer1 in), h2 in g_h0
    const __half* ins[3]  = { hx, hmax, h0 };
    __half* outs[3]       = { hmax, h0, nullptr };   // mode 0/1/2
    int gemm_grid = (M + 127) / 128;
    int agg_grid = (M * 32 + 255) / 256;
    for (int l = 0; l < LL; l++) {
        agg_kernel<<<agg_grid, 256>>>(ins[l], alpha, M);
        gemm_layer_f16<<<gemm_grid, 256>>>(
            ins[l],
            wt + (size_t)l * 3 * DD * DD,
            bself + (size_t)l * DD,
            bstd  + (size_t)l * DD,
            bdts  + (size_t)l * DD,
            alpha, outs[l], l, M);
    }

    // final linear (fp16 MMA)
    final_mma_kernel<<<(M + 127) / 128, 256, FINAL_SMEM>>>(blin, (float*)d_out, M);
}

// round 15
// speedup vs baseline: 1.0719x; 1.0143x over previous
#include <cuda_runtime.h>
#include <cuda_fp16.h>
#include <cuda_bf16.h>

#define NN 50000
#define EE 800000
#define DD 128
#define OO 64
#define LL 3

// ---------------- scratch (device globals) ----------------
__device__ __half g_hx[NN * DD];      // x converted to fp16
__device__ __half g_h0[NN * DD];      // h2 buffer
__device__ __half g_agg0[NN * DD];    // (1-a)/deg * sum_{src->dst}
__device__ __half g_agg1[NN * DD];    // a/deg * sum_{dst->src}
__device__ __half g_hmax[NN * DD];    // JK max (h1 lives here after layer 0)
__device__ __half g_Wt[LL * 3 * DD * DD];   // layer weights fp16, [mat][n][k]
__device__ __half g_Wlt[OO * DD];           // Wlin fp16, [n][k]

__device__ int g_deg[2 * NN];         // [0]=by dst, [1]=by src
__device__ int g_rp0[NN + 1];
__device__ int g_rp1[NN + 1];
__device__ int g_cur0[NN];
__device__ int g_cur1[NN];
__device__ int g_col0[EE];            // CSR by dst, values = src
__device__ int g_col1[EE];            // CSR by src, values = dst

// ---------------- helpers ----------------
__device__ __forceinline__ void cp16(__half* s, const void* g, bool v) {
    unsigned sa = (unsigned)__cvta_generic_to_shared(s);
    int sz = v ? 16 : 0;
    asm volatile("cp.async.ca.shared.global [%0], [%1], 16, %2;"
                 :: "r"(sa), "l"(g), "r"(sz));
}

__device__ __forceinline__ void ldsm_x4(unsigned& r0, unsigned& r1,
                                        unsigned& r2, unsigned& r3,
                                        const __half* p) {
    unsigned addr = (unsigned)__cvta_generic_to_shared(p);
    asm volatile("ldmatrix.sync.aligned.m8n8.x4.shared.b16 {%0,%1,%2,%3}, [%4];"
                 : "=r"(r0), "=r"(r1), "=r"(r2), "=r"(r3) : "r"(addr));
}

// ---------------- CSR build ----------------
__global__ void count_kernel(const int* __restrict__ ei, int E) {
    int e = blockIdx.x * blockDim.x + threadIdx.x;
    if (e >= E) return;
    int src = ei[e];
    int dst = ei[E + e];
    atomicAdd(&g_deg[dst], 1);
    atomicAdd(&g_deg[NN + src], 1);
}

__global__ void scan_kernel(int n) {
    const int* deg = g_deg + blockIdx.x * NN;
    int* rp = (blockIdx.x == 0) ? g_rp0 : g_rp1;
    int* cur = (blockIdx.x == 0) ? g_cur0 : g_cur1;

    __shared__ int sums[1024];
    int t = threadIdx.x;
    int chunk = (n + 1023) / 1024;
    int begin = t * chunk;
    int end = min(begin + chunk, n);
    int s = 0;
    for (int i = begin; i < end; i++) s += deg[i];
    sums[t] = s;
    __syncthreads();
    for (int off = 1; off < 1024; off <<= 1) {
        int v = (t >= off) ? sums[t - off] : 0;
        __syncthreads();
        sums[t] += v;
        __syncthreads();
    }
    int prefix = (t == 0) ? 0 : sums[t - 1];
    for (int i = begin; i < end; i++) {
        rp[i] = prefix;
        cur[i] = prefix;
        prefix += deg[i];
    }
    if (t == 1023) rp[n] = prefix;
}

// fused: CSR fill | x->fp16 convert | weight transpose+convert
__global__ void fill_convert_prep_kernel(
    const int* __restrict__ ei, int E,
    const float* __restrict__ x, int total4,
    const float* __restrict__ Wself, const float* __restrict__ Wstd,
    const float* __restrict__ Wdts, const float* __restrict__ Wlin,
    int fillBlocks, int convBlocks)
{
    int b = blockIdx.x;
    if (b < fillBlocks) {
        int e = b * blockDim.x + threadIdx.x;
        if (e >= E) return;
        int src = ei[e];
        int dst = ei[E + e];
        int p0 = atomicAdd(&g_cur0[dst], 1);
        g_col0[p0] = src;
        int p1 = atomicAdd(&g_cur1[src], 1);
        g_col1[p1] = dst;
    } else if (b < fillBlocks + convBlocks) {
        int i = (b - fillBlocks) * blockDim.x + threadIdx.x;
        if (i >= total4) return;
        float4 v = ((const float4*)x)[i];
        __half2 h0 = __floats2half2_rn(v.x, v.y);
        __half2 h1 = __floats2half2_rn(v.z, v.w);
        uint2 u;
        u.x = *(unsigned*)&h0;
        u.y = *(unsigned*)&h1;
        ((uint2*)g_hx)[i] = u;
    } else {
        int idx = (b - fillBlocks - convBlocks) * blockDim.x + threadIdx.x;
        if (idx < LL * 3 * DD * DD) {
            int mat = idx >> 14;
            int r = (idx >> 7) & 127;
            int c = idx & 127;
            int l = mat / 3, s = mat % 3;
            const float* W = (s == 0) ? Wself : (s == 1) ? Wstd : Wdts;
            float v = W[(size_t)l * DD * DD + r * DD + c];
            g_Wt[(size_t)mat * DD * DD + c * DD + r] = __float2half(v);
        } else {
            int i2 = idx - LL * 3 * DD * DD;
            if (i2 < OO * DD) {
                int n = i2 >> 7;
                int k = i2 & 127;
                g_Wlt[n * DD + k] = __float2half(Wlin[k * OO + n]);
            }
        }
    }
}

// ---------------- aggregation: one warp per node, 4-deep fp16 tree ---------
__device__ __forceinline__ __half2 u2h(unsigned u) { return *(__half2*)&u; }

__global__ void agg_kernel(const __half* __restrict__ h,
                           const float* __restrict__ alpha, int M) {
    int gw = (blockIdx.x * blockDim.x + threadIdx.x) >> 5;
    if (gw >= M) return;
    int lane = threadIdx.x & 31;
    int base = lane * 4;   // halves
    float a = alpha[0];

    #pragma unroll
    for (int dir = 0; dir < 2; dir++) {
        const int* rp  = dir ? g_rp1  : g_rp0;
        const int* col = dir ? g_col1 : g_col0;
        __half* out    = dir ? g_agg1 : g_agg0;
        float coef     = dir ? a : (1.f - a);

        int s = rp[gw], e = rp[gw + 1];
        float4 acc = make_float4(0.f, 0.f, 0.f, 0.f);
        int i = s;
        for (; i + 3 < e; i += 4) {
            int n0 = col[i],     n1 = col[i + 1];
            int n2 = col[i + 2], n3 = col[i + 3];
            uint2 u0 = *(const uint2*)(h + (size_t)n0 * DD + base);
            uint2 u1 = *(const uint2*)(h + (size_t)n1 * DD + base);
            uint2 u2 = *(const uint2*)(h + (size_t)n2 * DD + base);
            uint2 u3 = *(const uint2*)(h + (size_t)n3 * DD + base);
            __half2 s0 = __hadd2(__hadd2(u2h(u0.x), u2h(u1.x)),
                                 __hadd2(u2h(u2.x), u2h(u3.x)));
            __half2 s1 = __hadd2(__hadd2(u2h(u0.y), u2h(u1.y)),
                                 __hadd2(u2h(u2.y), u2h(u3.y)));
            float2 f0 = __half22float2(s0);
            float2 f1 = __half22float2(s1);
            acc.x += f0.x; acc.y += f0.y;
            acc.z += f1.x; acc.w += f1.y;
        }
        for (; i < e; i++) {
            int n0 = col[i];
            uint2 u0 = *(const uint2*)(h + (size_t)n0 * DD + base);
            float2 f0 = __half22float2(u2h(u0.x));
            float2 f1 = __half22float2(u2h(u0.y));
            acc.x += f0.x; acc.y += f0.y;
            acc.z += f1.x; acc.w += f1.y;
        }
        float sc = coef / fmaxf((float)(e - s), 1.f);
        __half2 o0 = __floats2half2_rn(acc.x * sc, acc.y * sc);
        __half2 o1 = __floats2half2_rn(acc.z * sc, acc.w * sc);
        uint2 u;
        u.x = *(unsigned*)&o0;
        u.y = *(unsigned*)&o1;
        *(uint2*)(out + (size_t)gw * DD + base) = u;
    }
}

// ---------------- fp16 tensor-core layer GEMM (cp.async + ldmatrix) --------
// mode: 0 = layer0 (write hmax only), 1 = mid layer (write Hout + max hmax),
//       2 = last layer (max hmax only)
#define SA 40   // smem row stride in halves

__global__ __launch_bounds__(256) void gemm_layer_f16(
    const __half* __restrict__ A0,
    const __half* __restrict__ Wt,   // layer base (3 mats)
    const float* __restrict__ bs0,
    const float* __restrict__ bs1,
    const float* __restrict__ bs2,
    const float* __restrict__ alpha,
    __half* __restrict__ Hout,
    int mode, int M)
{
    __shared__ __align__(16) __half As[2][128 * SA];
    __shared__ __align__(16) __half Bs[2][128 * SA];
    __shared__ float bias_s[DD];

    int tid = threadIdx.x;
    int block_row = blockIdx.x * 128;
    int warpId = tid >> 5;
    int lane = tid & 31;
    int g = lane >> 2;
    int t = lane & 3;
    int warp_row = warpId & 3;
    int warp_col = warpId >> 2;

    if (tid < DD) {
        float a = alpha[0];
        bias_s[tid] = bs0[tid] + (1.f - a) * bs1[tid] + a * bs2[tid];
    }

    // ldmatrix lane address components (verified mapping, R6)
    int lm_row8 = lane & 7;
    int a_roff = lm_row8 + ((lane >> 3) & 1) * 8;   // row within 16
    int a_koff = (lane >> 4) * 8;                   // 0 or 8
    int b_noff = lm_row8 + ((lane >> 4) & 1) * 8;   // n within 16
    int b_koff = ((lane >> 3) & 1) * 8;             // 0 or 8

    float acc[2][8][4];
    #pragma unroll
    for (int mt = 0; mt < 2; mt++)
        #pragma unroll
        for (int nt = 0; nt < 8; nt++)
            #pragma unroll
            for (int r = 0; r < 4; r++) acc[mt][nt][r] = 0.f;

    const __half* Aseg[3] = { A0, g_agg0, g_agg1 };

    int l_row = tid >> 2;          // 0..63
    int l_kq = (tid & 3) * 8;      // halves: 0,8,16,24

    auto cp_chunk = [&](int c, int buf) {
        int seg = c >> 2;
        int kl = (c & 3) * 32;
        const __half* A = Aseg[seg];
        const __half* B = Wt + (size_t)seg * DD * DD;
        #pragma unroll
        for (int j = 0; j < 2; j++) {
            int row = l_row + j * 64;
            int gr = block_row + row;
            cp16(&As[buf][row * SA + l_kq], A + (size_t)gr * DD + kl + l_kq, gr < M);
            cp16(&Bs[buf][row * SA + l_kq], B + (size_t)row * DD + kl + l_kq, true);
        }
        asm volatile("cp.async.commit_group;");
    };

    cp_chunk(0, 0);

    #pragma unroll 1
    for (int c = 0; c < 12; c++) {
        int buf = c & 1;
        if (c < 11) {
            cp_chunk(c + 1, buf ^ 1);
            asm volatile("cp.async.wait_group 1;");
        } else {
            asm volatile("cp.async.wait_group 0;");
        }
        __syncthreads();

        #pragma unroll
        for (int ks = 0; ks < 2; ks++) {
            int k0 = ks * 16;
            unsigned af[2][4];
            #pragma unroll
            for (int mt = 0; mt < 2; mt++) {
                int mrow = warp_row * 32 + mt * 16;
                ldsm_x4(af[mt][0], af[mt][1], af[mt][2], af[mt][3],
                        &As[buf][(mrow + a_roff) * SA + k0 + a_koff]);
            }
            unsigned bf[8][2];
            #pragma unroll
            for (int np = 0; np < 4; np++) {
                int n0 = warp_col * 64 + np * 16;
                ldsm_x4(bf[np * 2][0], bf[np * 2][1], bf[np * 2 + 1][0], bf[np * 2 + 1][1],
                        &Bs[buf][(n0 + b_noff) * SA + k0 + b_koff]);
            }
            #pragma unroll
            for (int mt = 0; mt < 2; mt++)
                #pragma unroll
                for (int nt = 0; nt < 8; nt++) {
                    asm volatile(
                        "mma.sync.aligned.m16n8k16.row.col.f32.f16.f16.f32 "
                        "{%0,%1,%2,%3}, {%4,%5,%6,%7}, {%8,%9}, {%0,%1,%2,%3};"
                        : "+f"(acc[mt][nt][0]), "+f"(acc[mt][nt][1]),
                          "+f"(acc[mt][nt][2]), "+f"(acc[mt][nt][3])
                        : "r"(af[mt][0]), "r"(af[mt][1]), "r"(af[mt][2]), "r"(af[mt][3]),
                          "r"(bf[nt][0]), "r"(bf[nt][1]));
                }
        }
        __syncthreads();
    }

    // epilogue: bias + relu; store per mode
    #pragma unroll
    for (int mt = 0; mt < 2; mt++) {
        #pragma unroll
        for (int nt = 0; nt < 8; nt++) {
            int c0 = warp_col * 64 + nt * 8 + 2 * t;
            float b0v = bias_s[c0];
            float b1v = bias_s[c0 + 1];
            #pragma unroll
            for (int rr = 0; rr < 2; rr++) {
                int r = block_row + warp_row * 32 + mt * 16 + g + rr * 8;
                if (r < M) {
                    float v0 = fmaxf(acc[mt][nt][rr * 2 + 0] + b0v, 0.f);
                    float v1 = fmaxf(acc[mt][nt][rr * 2 + 1] + b1v, 0.f);
                    __half2 hv = __floats2half2_rn(v0, v1);
                    __half2* mp = (__half2*)(g_hmax + (size_t)r * DD + c0);
                    if (mode == 0) {
                        *mp = hv;                 // h1 lives in hmax
                    } else {
                        if (mode == 1)
                            *(__half2*)(Hout + (size_t)r * DD + c0) = hv;
                        *mp = __hmax2(*mp, hv);
                    }
                }
            }
        }
    }
}

// ---------------- final linear via fp16 MMA: hmax @ Wlt^T + blin ------------
#define SF 136

__global__ __launch_bounds__(256) void final_mma_kernel(
    const float* __restrict__ blin, float* __restrict__ out, int M)
{
    extern __shared__ char dynsm[];
    float* bias_s = (float*)dynsm;
    __half* As = (__half*)(dynsm + 256);
    __half* Bs = As + 128 * SF;

    int tid = threadIdx.x;
    int block_row = blockIdx.x * 128;
    int warpId = tid >> 5;
    int lane = tid & 31;
    int g = lane >> 2;
    int t = lane & 3;
    int warp_row = warpId & 3;
    int warp_col = warpId >> 2;

    if (tid < OO) bias_s[tid] = blin[tid];

    #pragma unroll
    for (int k = 0; k < 8; k++) {
        int idx = tid + k * 256;
        int row = idx >> 4;
        int q = (idx & 15) * 8;
        int gr = block_row + row;
        uint4 v = make_uint4(0u, 0u, 0u, 0u);
        if (gr < M) v = *(const uint4*)(g_hmax + (size_t)gr * DD + q);
        *(uint4*)&As[row * SF + q] = v;
    }
    #pragma unroll
    for (int k = 0; k < 4; k++) {
        int idx = tid + k * 256;
        int row = idx >> 4;
        int q = (idx & 15) * 8;
        *(uint4*)&Bs[row * SF + q] = *(const uint4*)(g_Wlt + row * DD + q);
    }
    __syncthreads();

    float acc[2][4][4];
    #pragma unroll
    for (int mt = 0; mt < 2; mt++)
        #pragma unroll
        for (int nt = 0; nt < 4; nt++)
            #pragma unroll
            for (int r = 0; r < 4; r++) acc[mt][nt][r] = 0.f;

    #pragma unroll
    for (int kc = 0; kc < 8; kc++) {
        int k0 = kc * 16;
        unsigned af[2][4];
        #pragma unroll
        for (int mt = 0; mt < 2; mt++) {
            int mrow = warp_row * 32 + mt * 16;
            af[mt][0] = *(const unsigned*)&As[(mrow + g) * SF + k0 + 2 * t];
            af[mt][1] = *(const unsigned*)&As[(mrow + g + 8) * SF + k0 + 2 * t];
            af[mt][2] = *(const unsigned*)&As[(mrow + g) * SF + k0 + 8 + 2 * t];
            af[mt][3] = *(const unsigned*)&As[(mrow + g + 8) * SF + k0 + 8 + 2 * t];
        }
        unsigned bf[4][2];
        #pragma unroll
        for (int nt = 0; nt < 4; nt++) {
            int n = warp_col * 32 + nt * 8 + g;
            bf[nt][0] = *(const unsigned*)&Bs[n * SF + k0 + 2 * t];
            bf[nt][1] = *(const unsigned*)&Bs[n * SF + k0 + 8 + 2 * t];
        }
        #pragma unroll
        for (int mt = 0; mt < 2; mt++)
            #pragma unroll
            for (int nt = 0; nt < 4; nt++) {
                asm volatile(
                    "mma.sync.aligned.m16n8k16.row.col.f32.f16.f16.f32 "
                    "{%0,%1,%2,%3}, {%4,%5,%6,%7}, {%8,%9}, {%0,%1,%2,%3};"
                    : "+f"(acc[mt][nt][0]), "+f"(acc[mt][nt][1]),
                      "+f"(acc[mt][nt][2]), "+f"(acc[mt][nt][3])
                    : "r"(af[mt][0]), "r"(af[mt][1]), "r"(af[mt][2]), "r"(af[mt][3]),
                      "r"(bf[nt][0]), "r"(bf[nt][1]));
            }
    }

    #pragma unroll
    for (int mt = 0; mt < 2; mt++) {
        #pragma unroll
        for (int nt = 0; nt < 4; nt++) {
            int c0 = warp_col * 32 + nt * 8 + 2 * t;
            float b0v = bias_s[c0];
            float b1v = bias_s[c0 + 1];
            #pragma unroll
            for (int rr = 0; rr < 2; rr++) {
                int r = block_row + warp_row * 32 + mt * 16 + g + rr * 8;
                if (r < M) {
                    float2 o;
                    o.x = acc[mt][nt][rr * 2 + 0] + b0v;
                    o.y = acc[mt][nt][rr * 2 + 1] + b1v;
                    *(float2*)(out + (size_t)r * OO + c0) = o;
                }
            }
        }
    }
}

// ---------------- launch ----------------
extern "C" void kernel_launch(void* const* d_in, const int* in_sizes, int n_in,
                              void* d_out, int out_size) {
    const float* x     = (const float*)d_in[0];
    const int*   ei    = (const int*)d_in[1];
    const float* Wself = (const float*)d_in[2];
    const float* bself = (const float*)d_in[3];
    const float* Wstd  = (const float*)d_in[4];
    const float* bstd  = (const float*)d_in[5];
    const float* Wdts  = (const float*)d_in[6];
    const float* bdts  = (const float*)d_in[7];
    const float* Wlin  = (const float*)d_in[8];
    const float* blin  = (const float*)d_in[9];
    const float* alpha = (const float*)d_in[10];

    int M = in_sizes[0] / DD;        // 50000
    int E = in_sizes[1] / 2;         // 800000

    __half* hx;   cudaGetSymbolAddress((void**)&hx, g_hx);
    __half* h0;   cudaGetSymbolAddress((void**)&h0, g_h0);
    __half* hmax; cudaGetSymbolAddress((void**)&hmax, g_hmax);
    __half* wt;   cudaGetSymbolAddress((void**)&wt, g_Wt);
    int* degp;    cudaGetSymbolAddress((void**)&degp, g_deg);

    const int FINAL_SMEM = 256 + (128 * SF + 64 * SF) * 2;   // 52480
    cudaFuncSetAttribute(final_mma_kernel,
                         cudaFuncAttributeMaxDynamicSharedMemorySize, FINAL_SMEM);

    cudaMemsetAsync(degp, 0, 2 * NN * sizeof(int));

    count_kernel<<<(E + 255) / 256, 256>>>(ei, E);
    scan_kernel<<<2, 1024>>>(M);
    int total4 = M * DD / 4;
    int fillBlocks = (E + 255) / 256;
    int convBlocks = (total4 + 255) / 256;
    int prepBlocks = (LL * 3 * DD * DD + OO * DD + 255) / 256;
    fill_convert_prep_kernel<<<fillBlocks + convBlocks + prepBlocks, 256>>>(
        ei, E, x, total4, Wself, Wstd, Wdts, Wlin, fillBlocks, convBlocks);

    // layers: h1 lives in g_hmax (layer0 out, layer1 in), h2 in g_h0
    const __half* ins[3]  = { hx, hmax, h0 };
    __half* outs[3]       = { hmax, h0, nullptr };   // mode 0/1/2
    int gemm_grid = (M + 127) / 128;
    int agg_grid = (M * 32 + 255) / 256;
    for (int l = 0; l < LL; l++) {
        agg_kernel<<<agg_grid, 256>>>(ins[l], alpha, M);
        gemm_layer_f16<<<gemm_grid, 256>>>(
            ins[l],
            wt + (size_t)l * 3 * DD * DD,
            bself + (size_t)l * DD,
            bstd  + (size_t)l * DD,
            bdts  + (size_t)l * DD,
            alpha, outs[l], l, M);
    }

    // final linear (fp16 MMA)
    final_mma_kernel<<<(M + 127) / 128, 256, FINAL_SMEM>>>(blin, (float*)d_out, M);
}

// round 16
// speedup vs baseline: 1.0837x; 1.0110x over previous
#include <cuda_runtime.h>
#include <cuda_fp16.h>
#include <cuda_bf16.h>

#define NN 50000
#define EE 800000
#define DD 128
#define OO 64
#define LL 3

// ---------------- scratch (device globals) ----------------
__device__ __half g_hx[NN * DD];      // x converted to fp16
__device__ __half g_h0[NN * DD];      // h2 buffer
__device__ __half g_agg0[NN * DD];    // (1-a)/deg * sum_{src->dst}
__device__ __half g_agg1[NN * DD];    // a/deg * sum_{dst->src}
__device__ __half g_hmax[NN * DD];    // JK max (h1 lives here after layer 0)
__device__ __half g_Wt[LL * 3 * DD * DD];   // layer weights fp16, [mat][n][k]
__device__ __half g_Wlt[OO * DD];           // Wlin fp16, [n][k]

__device__ int g_deg[2 * NN];         // [0]=by dst, [1]=by src
__device__ int g_rp0[NN + 1];
__device__ int g_rp1[NN + 1];
__device__ int g_cur0[NN];
__device__ int g_cur1[NN];
__device__ int g_col0[EE];            // CSR by dst, values = src
__device__ int g_col1[EE];            // CSR by src, values = dst

// ---------------- helpers ----------------
__device__ __forceinline__ void cp16(__half* s, const void* g, bool v) {
    unsigned sa = (unsigned)__cvta_generic_to_shared(s);
    int sz = v ? 16 : 0;
    asm volatile("cp.async.ca.shared.global [%0], [%1], 16, %2;"
                 :: "r"(sa), "l"(g), "r"(sz));
}

__device__ __forceinline__ void ldsm_x4(unsigned& r0, unsigned& r1,
                                        unsigned& r2, unsigned& r3,
                                        const __half* p) {
    unsigned addr = (unsigned)__cvta_generic_to_shared(p);
    asm volatile("ldmatrix.sync.aligned.m8n8.x4.shared.b16 {%0,%1,%2,%3}, [%4];"
                 : "=r"(r0), "=r"(r1), "=r"(r2), "=r"(r3) : "r"(addr));
}

// ---------------- CSR build ----------------
__global__ void count_kernel(const int* __restrict__ ei, int E) {
    int e = blockIdx.x * blockDim.x + threadIdx.x;
    if (e >= E) return;
    int src = ei[e];
    int dst = ei[E + e];
    atomicAdd(&g_deg[dst], 1);
    atomicAdd(&g_deg[NN + src], 1);
}

__global__ void scan_kernel(int n) {
    const int* deg = g_deg + blockIdx.x * NN;
    int* rp = (blockIdx.x == 0) ? g_rp0 : g_rp1;
    int* cur = (blockIdx.x == 0) ? g_cur0 : g_cur1;

    __shared__ int sums[1024];
    int t = threadIdx.x;
    int chunk = (n + 1023) / 1024;
    int begin = t * chunk;
    int end = min(begin + chunk, n);
    int s = 0;
    for (int i = begin; i < end; i++) s += deg[i];
    sums[t] = s;
    __syncthreads();
    for (int off = 1; off < 1024; off <<= 1) {
        int v = (t >= off) ? sums[t - off] : 0;
        __syncthreads();
        sums[t] += v;
        __syncthreads();
    }
    int prefix = (t == 0) ? 0 : sums[t - 1];
    for (int i = begin; i < end; i++) {
        rp[i] = prefix;
        cur[i] = prefix;
        prefix += deg[i];
    }
    if (t == 1023) rp[n] = prefix;
}

// fused: CSR fill | x->fp16 convert | weight transpose+convert
__global__ void fill_convert_prep_kernel(
    const int* __restrict__ ei, int E,
    const float* __restrict__ x, int total4,
    const float* __restrict__ Wself, const float* __restrict__ Wstd,
    const float* __restrict__ Wdts, const float* __restrict__ Wlin,
    int fillBlocks, int convBlocks)
{
    int b = blockIdx.x;
    if (b < fillBlocks) {
        int e = b * blockDim.x + threadIdx.x;
        if (e >= E) return;
        int src = ei[e];
        int dst = ei[E + e];
        int p0 = atomicAdd(&g_cur0[dst], 1);
        g_col0[p0] = src;
        int p1 = atomicAdd(&g_cur1[src], 1);
        g_col1[p1] = dst;
    } else if (b < fillBlocks + convBlocks) {
        int i = (b - fillBlocks) * blockDim.x + threadIdx.x;
        if (i >= total4) return;
        float4 v = ((const float4*)x)[i];
        __half2 h0 = __floats2half2_rn(v.x, v.y);
        __half2 h1 = __floats2half2_rn(v.z, v.w);
        uint2 u;
        u.x = *(unsigned*)&h0;
        u.y = *(unsigned*)&h1;
        ((uint2*)g_hx)[i] = u;
    } else {
        int idx = (b - fillBlocks - convBlocks) * blockDim.x + threadIdx.x;
        if (idx < LL * 3 * DD * DD) {
            int mat = idx >> 14;
            int r = (idx >> 7) & 127;
            int c = idx & 127;
            int l = mat / 3, s = mat % 3;
            const float* W = (s == 0) ? Wself : (s == 1) ? Wstd : Wdts;
            float v = W[(size_t)l * DD * DD + r * DD + c];
            g_Wt[(size_t)mat * DD * DD + c * DD + r] = __float2half(v);
        } else {
            int i2 = idx - LL * 3 * DD * DD;
            if (i2 < OO * DD) {
                int n = i2 >> 7;
                int k = i2 & 127;
                g_Wlt[n * DD + k] = __float2half(Wlin[k * OO + n]);
            }
        }
    }
}

// ---------------- aggregation: one warp per node, 4-deep fp16 tree ---------
__device__ __forceinline__ __half2 u2h(unsigned u) { return *(__half2*)&u; }

__global__ void agg_kernel(const __half* __restrict__ h,
                           const float* __restrict__ alpha, int M) {
    int gw = (blockIdx.x * blockDim.x + threadIdx.x) >> 5;
    if (gw >= M) return;
    int lane = threadIdx.x & 31;
    int base = lane * 4;   // halves
    float a = alpha[0];

    #pragma unroll
    for (int dir = 0; dir < 2; dir++) {
        const int* rp  = dir ? g_rp1  : g_rp0;
        const int* col = dir ? g_col1 : g_col0;
        __half* out    = dir ? g_agg1 : g_agg0;
        float coef     = dir ? a : (1.f - a);

        int s = rp[gw], e = rp[gw + 1];
        float4 acc = make_float4(0.f, 0.f, 0.f, 0.f);
        int i = s;
        for (; i + 3 < e; i += 4) {
            int n0 = col[i],     n1 = col[i + 1];
            int n2 = col[i + 2], n3 = col[i + 3];
            uint2 u0 = *(const uint2*)(h + (size_t)n0 * DD + base);
            uint2 u1 = *(const uint2*)(h + (size_t)n1 * DD + base);
            uint2 u2 = *(const uint2*)(h + (size_t)n2 * DD + base);
            uint2 u3 = *(const uint2*)(h + (size_t)n3 * DD + base);
            __half2 s0 = __hadd2(__hadd2(u2h(u0.x), u2h(u1.x)),
                                 __hadd2(u2h(u2.x), u2h(u3.x)));
            __half2 s1 = __hadd2(__hadd2(u2h(u0.y), u2h(u1.y)),
                                 __hadd2(u2h(u2.y), u2h(u3.y)));
            float2 f0 = __half22float2(s0);
            float2 f1 = __half22float2(s1);
            acc.x += f0.x; acc.y += f0.y;
            acc.z += f1.x; acc.w += f1.y;
        }
        for (; i < e; i++) {
            int n0 = col[i];
            uint2 u0 = *(const uint2*)(h + (size_t)n0 * DD + base);
            float2 f0 = __half22float2(u2h(u0.x));
            float2 f1 = __half22float2(u2h(u0.y));
            acc.x += f0.x; acc.y += f0.y;
            acc.z += f1.x; acc.w += f1.y;
        }
        float sc = coef / fmaxf((float)(e - s), 1.f);
        __half2 o0 = __floats2half2_rn(acc.x * sc, acc.y * sc);
        __half2 o1 = __floats2half2_rn(acc.z * sc, acc.w * sc);
        uint2 u;
        u.x = *(unsigned*)&o0;
        u.y = *(unsigned*)&o1;
        *(uint2*)(out + (size_t)gw * DD + base) = u;
    }
}

// ---------------- fp16 tensor-core layer GEMM (3-stage cp.async + ldmatrix) -
// mode: 0 = layer0 (write hmax only), 1 = mid layer (write Hout + max hmax),
//       2 = last layer (max hmax only)
#define SA 40   // smem row stride in halves
#define GEMM_SMEM (512 + 3 * 128 * SA * 2 * 2 + 256)   // bias + 3*(As+Bs) stages

__global__ __launch_bounds__(256) void gemm_layer_f16(
    const __half* __restrict__ A0,
    const __half* __restrict__ Wt,   // layer base (3 mats)
    const float* __restrict__ bs0,
    const float* __restrict__ bs1,
    const float* __restrict__ bs2,
    const float* __restrict__ alpha,
    __half* __restrict__ Hout,
    int mode, int M)
{
    extern __shared__ char dynsm[];
    float* bias_s = (float*)dynsm;                         // 512B
    __half* AsBase = (__half*)(dynsm + 512);               // 3 * 128*SA
    __half* BsBase = AsBase + 3 * 128 * SA;                // 3 * 128*SA

    int tid = threadIdx.x;
    int block_row = blockIdx.x * 128;
    int warpId = tid >> 5;
    int lane = tid & 31;
    int g = lane >> 2;
    int t = lane & 3;
    int warp_row = warpId & 3;
    int warp_col = warpId >> 2;

    if (tid < DD) {
        float a = alpha[0];
        bias_s[tid] = bs0[tid] + (1.f - a) * bs1[tid] + a * bs2[tid];
    }

    // ldmatrix lane address components
    int lm_row8 = lane & 7;
    int a_roff = lm_row8 + ((lane >> 3) & 1) * 8;
    int a_koff = (lane >> 4) * 8;
    int b_noff = lm_row8 + ((lane >> 4) & 1) * 8;
    int b_koff = ((lane >> 3) & 1) * 8;

    float acc[2][8][4];
    #pragma unroll
    for (int mt = 0; mt < 2; mt++)
        #pragma unroll
        for (int nt = 0; nt < 8; nt++)
            #pragma unroll
            for (int r = 0; r < 4; r++) acc[mt][nt][r] = 0.f;

    const __half* Aseg[3] = { A0, g_agg0, g_agg1 };

    int l_row = tid >> 2;          // 0..63
    int l_kq = (tid & 3) * 8;      // halves: 0,8,16,24

    auto cp_chunk = [&](int c, int buf) {
        int seg = c >> 2;
        int kl = (c & 3) * 32;
        const __half* A = Aseg[seg];
        const __half* B = Wt + (size_t)seg * DD * DD;
        __half* As = AsBase + buf * 128 * SA;
        __half* Bs = BsBase + buf * 128 * SA;
        #pragma unroll
        for (int j = 0; j < 2; j++) {
            int row = l_row + j * 64;
            int gr = block_row + row;
            cp16(&As[row * SA + l_kq], A + (size_t)gr * DD + kl + l_kq, gr < M);
            cp16(&Bs[row * SA + l_kq], B + (size_t)row * DD + kl + l_kq, true);
        }
        asm volatile("cp.async.commit_group;");
    };

    cp_chunk(0, 0);
    cp_chunk(1, 1);

    #pragma unroll 1
    for (int c = 0; c < 12; c++) {
        int buf = c % 3;
        if (c < 11) {
            asm volatile("cp.async.wait_group 1;");
        } else {
            asm volatile("cp.async.wait_group 0;");
        }
        __syncthreads();     // chunk c ready; all warps done with MMA(c-1)
        if (c < 10) cp_chunk(c + 2, (c + 2) % 3);   // overwrites buf of c-1 (safe)

        const __half* As = AsBase + buf * 128 * SA;
        const __half* Bs = BsBase + buf * 128 * SA;

        #pragma unroll
        for (int ks = 0; ks < 2; ks++) {
            int k0 = ks * 16;
            unsigned af[2][4];
            #pragma unroll
            for (int mt = 0; mt < 2; mt++) {
                int mrow = warp_row * 32 + mt * 16;
                ldsm_x4(af[mt][0], af[mt][1], af[mt][2], af[mt][3],
                        &As[(mrow + a_roff) * SA + k0 + a_koff]);
            }
            unsigned bf[8][2];
            #pragma unroll
            for (int np = 0; np < 4; np++) {
                int n0 = warp_col * 64 + np * 16;
                ldsm_x4(bf[np * 2][0], bf[np * 2][1], bf[np * 2 + 1][0], bf[np * 2 + 1][1],
                        &Bs[(n0 + b_noff) * SA + k0 + b_koff]);
            }
            #pragma unroll
            for (int mt = 0; mt < 2; mt++)
                #pragma unroll
                for (int nt = 0; nt < 8; nt++) {
                    asm volatile(
                        "mma.sync.aligned.m16n8k16.row.col.f32.f16.f16.f32 "
                        "{%0,%1,%2,%3}, {%4,%5,%6,%7}, {%8,%9}, {%0,%1,%2,%3};"
                        : "+f"(acc[mt][nt][0]), "+f"(acc[mt][nt][1]),
                          "+f"(acc[mt][nt][2]), "+f"(acc[mt][nt][3])
                        : "r"(af[mt][0]), "r"(af[mt][1]), "r"(af[mt][2]), "r"(af[mt][3]),
                          "r"(bf[nt][0]), "r"(bf[nt][1]));
                }
        }
    }

    // epilogue: bias + relu; store per mode
    #pragma unroll
    for (int mt = 0; mt < 2; mt++) {
        #pragma unroll
        for (int nt = 0; nt < 8; nt++) {
            int c0 = warp_col * 64 + nt * 8 + 2 * t;
            float b0v = bias_s[c0];
            float b1v = bias_s[c0 + 1];
            #pragma unroll
            for (int rr = 0; rr < 2; rr++) {
                int r = block_row + warp_row * 32 + mt * 16 + g + rr * 8;
                if (r < M) {
                    float v0 = fmaxf(acc[mt][nt][rr * 2 + 0] + b0v, 0.f);
                    float v1 = fmaxf(acc[mt][nt][rr * 2 + 1] + b1v, 0.f);
                    __half2 hv = __floats2half2_rn(v0, v1);
                    __half2* mp = (__half2*)(g_hmax + (size_t)r * DD + c0);
                    if (mode == 0) {
                        *mp = hv;                 // h1 lives in hmax
                    } else {
                        if (mode == 1)
                            *(__half2*)(Hout + (size_t)r * DD + c0) = hv;
                        *mp = __hmax2(*mp, hv);
                    }
                }
            }
        }
    }
}

// ---------------- final linear via fp16 MMA: hmax @ Wlt^T + blin ------------
#define SF 136

__global__ __launch_bounds__(256) void final_mma_kernel(
    const float* __restrict__ blin, float* __restrict__ out, int M)
{
    extern __shared__ char dynsm[];
    float* bias_s = (float*)dynsm;
    __half* As = (__half*)(dynsm + 256);
    __half* Bs = As + 128 * SF;

    int tid = threadIdx.x;
    int block_row = blockIdx.x * 128;
    int warpId = tid >> 5;
    int lane = tid & 31;
    int g = lane >> 2;
    int t = lane & 3;
    int warp_row = warpId & 3;
    int warp_col = warpId >> 2;

    if (tid < OO) bias_s[tid] = blin[tid];

    #pragma unroll
    for (int k = 0; k < 8; k++) {
        int idx = tid + k * 256;
        int row = idx >> 4;
        int q = (idx & 15) * 8;
        int gr = block_row + row;
        uint4 v = make_uint4(0u, 0u, 0u, 0u);
        if (gr < M) v = *(const uint4*)(g_hmax + (size_t)gr * DD + q);
        *(uint4*)&As[row * SF + q] = v;
    }
    #pragma unroll
    for (int k = 0; k < 4; k++) {
        int idx = tid + k * 256;
        int row = idx >> 4;
        int q = (idx & 15) * 8;
        *(uint4*)&Bs[row * SF + q] = *(const uint4*)(g_Wlt + row * DD + q);
    }
    __syncthreads();

    float acc[2][4][4];
    #pragma unroll
    for (int mt = 0; mt < 2; mt++)
        #pragma unroll
        for (int nt = 0; nt < 4; nt++)
            #pragma unroll
            for (int r = 0; r < 4; r++) acc[mt][nt][r] = 0.f;

    #pragma unroll
    for (int kc = 0; kc < 8; kc++) {
        int k0 = kc * 16;
        unsigned af[2][4];
        #pragma unroll
        for (int mt = 0; mt < 2; mt++) {
            int mrow = warp_row * 32 + mt * 16;
            af[mt][0] = *(const unsigned*)&As[(mrow + g) * SF + k0 + 2 * t];
            af[mt][1] = *(const unsigned*)&As[(mrow + g + 8) * SF + k0 + 2 * t];
            af[mt][2] = *(const unsigned*)&As[(mrow + g) * SF + k0 + 8 + 2 * t];
            af[mt][3] = *(const unsigned*)&As[(mrow + g + 8) * SF + k0 + 8 + 2 * t];
        }
        unsigned bf[4][2];
        #pragma unroll
        for (int nt = 0; nt < 4; nt++) {
            int n = warp_col * 32 + nt * 8 + g;
            bf[nt][0] = *(const unsigned*)&Bs[n * SF + k0 + 2 * t];
            bf[nt][1] = *(const unsigned*)&Bs[n * SF + k0 + 8 + 2 * t];
        }
        #pragma unroll
        for (int mt = 0; mt < 2; mt++)
            #pragma unroll
            for (int nt = 0; nt < 4; nt++) {
                asm volatile(
                    "mma.sync.aligned.m16n8k16.row.col.f32.f16.f16.f32 "
                    "{%0,%1,%2,%3}, {%4,%5,%6,%7}, {%8,%9}, {%0,%1,%2,%3};"
                    : "+f"(acc[mt][nt][0]), "+f"(acc[mt][nt][1]),
                      "+f"(acc[mt][nt][2]), "+f"(acc[mt][nt][3])
                    : "r"(af[mt][0]), "r"(af[mt][1]), "r"(af[mt][2]), "r"(af[mt][3]),
                      "r"(bf[nt][0]), "r"(bf[nt][1]));
            }
    }

    #pragma unroll
    for (int mt = 0; mt < 2; mt++) {
        #pragma unroll
        for (int nt = 0; nt < 4; nt++) {
            int c0 = warp_col * 32 + nt * 8 + 2 * t;
            float b0v = bias_s[c0];
            float b1v = bias_s[c0 + 1];
            #pragma unroll
            for (int rr = 0; rr < 2; rr++) {
                int r = block_row + warp_row * 32 + mt * 16 + g + rr * 8;
                if (r < M) {
                    float2 o;
                    o.x = acc[mt][nt][rr * 2 + 0] + b0v;
                    o.y = acc[mt][nt][rr * 2 + 1] + b1v;
                    *(float2*)(out + (size_t)r * OO + c0) = o;
                }
            }
        }
    }
}

// ---------------- launch ----------------
extern "C" void kernel_launch(void* const* d_in, const int* in_sizes, int n_in,
                              void* d_out, int out_size) {
    const float* x     = (const float*)d_in[0];
    const int*   ei    = (const int*)d_in[1];
    const float* Wself = (const float*)d_in[2];
    const float* bself = (const float*)d_in[3];
    const float* Wstd  = (const float*)d_in[4];
    const float* bstd  = (const float*)d_in[5];
    const float* Wdts  = (const float*)d_in[6];
    const float* bdts  = (const float*)d_in[7];
    const float* Wlin  = (const float*)d_in[8];
    const float* blin  = (const float*)d_in[9];
    const float* alpha = (const float*)d_in[10];

    int M = in_sizes[0] / DD;        // 50000
    int E = in_sizes[1] / 2;         // 800000

    __half* hx;   cudaGetSymbolAddress((void**)&hx, g_hx);
    __half* h0;   cudaGetSymbolAddress((void**)&h0, g_h0);
    __half* hmax; cudaGetSymbolAddress((void**)&hmax, g_hmax);
    __half* wt;   cudaGetSymbolAddress((void**)&wt, g_Wt);
    int* degp;    cudaGetSymbolAddress((void**)&degp, g_deg);

    const int FINAL_SMEM = 256 + (128 * SF + 64 * SF) * 2;   // 52480
    cudaFuncSetAttribute(final_mma_kernel,
                         cudaFuncAttributeMaxDynamicSharedMemorySize, FINAL_SMEM);
    cudaFuncSetAttribute(gemm_layer_f16,
                         cudaFuncAttributeMaxDynamicSharedMemorySize, GEMM_SMEM);

    cudaMemsetAsync(degp, 0, 2 * NN * sizeof(int));

    count_kernel<<<(E + 255) / 256, 256>>>(ei, E);
    scan_kernel<<<2, 1024>>>(M);
    int total4 = M * DD / 4;
    int fillBlocks = (E + 255) / 256;
    int convBlocks = (total4 + 255) / 256;
    int prepBlocks = (LL * 3 * DD * DD + OO * DD + 255) / 256;
    fill_convert_prep_kernel<<<fillBlocks + convBlocks + prepBlocks, 256>>>(
        ei, E, x, total4, Wself, Wstd, Wdts, Wlin, fillBlocks, convBlocks);

    // layers: h1 lives in g_hmax (layer0 out, layer1 in), h2 in g_h0
    const __half* ins[3]  = { hx, hmax, h0 };
    __half* outs[3]       = { hmax, h0, nullptr };   // mode 0/1/2
    int gemm_grid = (M + 127) / 128;
    int agg_grid = (M * 32 + 255) / 256;
    for (int l = 0; l < LL; l++) {
        agg_kernel<<<agg_grid, 256>>>(ins[l], alpha, M);
        gemm_layer_f16<<<gemm_grid, 256, GEMM_SMEM>>>(
            ins[l],
            wt + (size_t)l * 3 * DD * DD,
            bself + (size_t)l * DD,
            bstd  + (size_t)l * DD,
            bdts  + (size_t)l * DD,
            alpha, outs[l], l, M);
    }

    // final linear (fp16 MMA)
    final_mma_kernel<<<(M + 127) / 128, 256, FINAL_SMEM>>>(blin, (float*)d_out, M);
}